// round 9
// baseline (speedup 1.0000x reference)
#include <cuda_runtime.h>
#include <cuda_bf16.h>
#include <math.h>

// ---------------------------------------------------------------------------
// Problem constants
// ---------------------------------------------------------------------------
#define BATCH 4
#define IMG_H 512
#define IMG_W 512
#define PATCH 64
#define STRIDE_ 32
#define NPATCH 256
#define PATCHES_ELEMS (BATCH * NPATCH * 3 * PATCH * PATCH)   // 12,582,912
#define FLOW_ELEMS    (BATCH * 2 * IMG_H * IMG_W)            //  2,097,152

// Scratch (device globals). Each 33.5M floats = 67.1M bf16 = hi+lo planes.
__device__ __align__(256) float g_bufA[33554432];
__device__ __align__(256) float g_bufB[33554432];
#define PLANE_ELEMS 33554432

// Preconverted weights (bf16 hi/lo, pos16-permuted).
#define WSCRATCH 138240
__device__ __align__(256) __nv_bfloat16 g_wh[WSCRATCH];
__device__ __align__(256) __nv_bfloat16 g_wl[WSCRATCH];

// ---------------------------------------------------------------------------
// helpers
// ---------------------------------------------------------------------------
__device__ __forceinline__ void cp_async16(void* smem_dst, const void* gptr) {
    unsigned sa = (unsigned)__cvta_generic_to_shared(smem_dst);
    asm volatile("cp.async.cg.shared.global [%0], [%1], 16;" :: "r"(sa), "l"(gptr));
}
__device__ __forceinline__ void cp_commit() { asm volatile("cp.async.commit_group;"); }

__device__ __forceinline__ void mma16816(float* c, const unsigned* a, unsigned b0, unsigned b1) {
    asm volatile(
        "mma.sync.aligned.m16n8k16.row.col.f32.bf16.bf16.f32 "
        "{%0,%1,%2,%3}, {%4,%5,%6,%7}, {%8,%9}, {%0,%1,%2,%3};"
        : "+f"(c[0]), "+f"(c[1]), "+f"(c[2]), "+f"(c[3])
        : "r"(a[0]), "r"(a[1]), "r"(a[2]), "r"(a[3]), "r"(b0), "r"(b1));
}

// pos16(2q)=4q, pos16(2q+1)=4q+1, pos16(2q+8)=4q+2, pos16(2q+9)=4q+3 (q=0..3)
__device__ __forceinline__ int pos16(int ci) {
    return (((ci >> 1) & 3) << 2) + (((ci >> 3) & 1) << 1) + (ci & 1);
}
__device__ __forceinline__ void bf16split(float v, __nv_bfloat16& h, __nv_bfloat16& l) {
    h = __float2bfloat16(v);
    l = __float2bfloat16(v - __bfloat162float(h));
}

// ---------------------------------------------------------------------------
// Weight preconversion: fp32 [COUT][CIN][3][3] ->
// bf16 hi/lo planes [grp][cinblk][tap][co(COUTP)][pos16(ci)], zero-padded.
// ---------------------------------------------------------------------------
__global__ void wconv_kernel(const float* __restrict__ w,
                             __nv_bfloat16* __restrict__ dh,
                             __nv_bfloat16* __restrict__ dl,
                             int COUT, int CIN, int COUTP, int GRPS, int CBLKS)
{
    int total = GRPS * CBLKS * 9 * COUTP * 16;
    int idx = blockIdx.x * blockDim.x + threadIdx.x;
    if (idx >= total) return;
    int ci = idx & 15;
    int t = idx >> 4;
    int co = t % COUTP;  t /= COUTP;
    int tap = t % 9;     t /= 9;
    int cb = t % CBLKS;
    int grp = t / CBLKS;
    int co_g = grp * COUTP + co;
    int ci_g = cb * 16 + ci;
    float v = 0.f;
    if (co_g < COUT && ci_g < CIN)
        v = w[((size_t)co_g * CIN + ci_g) * 9 + tap];
    __nv_bfloat16 h, l;
    bf16split(v, h, l);
    int base = idx & ~15;
    dh[base + pos16(ci)] = h;
    dl[base + pos16(ci)] = l;
}

// ---------------------------------------------------------------------------
// x (fp32 NCHW, C=3) -> act layout [b][cb=0][y][x][pos16(ci)], ci>=3 zero
// ---------------------------------------------------------------------------
__global__ void xcvt_kernel(const float* __restrict__ x,
                            __nv_bfloat16* __restrict__ ohi,
                            __nv_bfloat16* __restrict__ olo)
{
    int idx = blockIdx.x * blockDim.x + threadIdx.x;
    int total = BATCH * IMG_H * IMG_W * 16;
    if (idx >= total) return;
    int ci = idx & 15;
    int p = idx >> 4;
    int xx = p % IMG_W;
    int yy = (p / IMG_W) % IMG_H;
    int b  = p / (IMG_W * IMG_H);
    float v = 0.f;
    if (ci < 3)
        v = x[((size_t)(b * 3 + ci) * IMG_H + yy) * IMG_W + xx];
    __nv_bfloat16 h, l;
    bf16split(v, h, l);
    size_t o = ((size_t)p << 4) + pos16(ci);
    ohi[o] = h;
    olo[o] = l;
}

// ---------------------------------------------------------------------------
// Implicit-GEMM 3x3 conv via mma.sync bf16 (3-term hi/lo split).
// Output tile per CTA: 32 wide x 8 tall x COUTP couts. 256 threads (8 warps).
// Double-buffered cp.async pipeline: chunk c+1 (input+weights) loads while
// chunk c computes.  Smem per CTA = 2 input bufs + 2 weight bufs -> occ 2.
// OUTF32=0: write bf16 hi/lo act layout (ACT=relu).  OUTF32=1: fp32 NCHW+tanh.
// ---------------------------------------------------------------------------
#define C_ROWS 10
#define C_PITCH 36
#define IN_PLANE (C_ROWS * C_PITCH * 16)    // 5760 bf16

template <int NCT>
__device__ __forceinline__ void stage_chunk(
    __nv_bfloat16* s_hi, __nv_bfloat16* s_lo,
    __nv_bfloat16* s_wh, __nv_bfloat16* s_wl,
    const __nv_bfloat16* __restrict__ ghi, const __nv_bfloat16* __restrict__ glo,
    const __nv_bfloat16* __restrict__ gwh, const __nv_bfloat16* __restrict__ gwl,
    int b, int grp, int cb, int CBIN, int bx, int by, int H, int W, int tid)
{
    constexpr int COUTP = NCT * 16;
    constexpr int WPL = 9 * COUTP * 16;
    // weights
    {
        const __nv_bfloat16* pwh = gwh + ((size_t)grp * CBIN + cb) * WPL;
        const __nv_bfloat16* pwl = gwl + ((size_t)grp * CBIN + cb) * WPL;
        for (int idx = tid * 8; idx < WPL; idx += 2048) {
            cp_async16(s_wh + idx, pwh + idx);
            cp_async16(s_wl + idx, pwl + idx);
        }
    }
    // input: 10 x 34 pixels, 32B per pixel per plane
    for (int p = tid; p < C_ROWS * 34; p += 256) {
        int row = p / 34;
        int col = p - row * 34;
        int gy = by + row - 1;
        int gx = bx + col - 1;
        int soff = (row * C_PITCH + col) * 16;
        if (gy >= 0 && gy < H && gx >= 0 && gx < W) {
            size_t g = ((((size_t)b * CBIN + cb) * H + gy) * W + gx) << 4;
            cp_async16(s_hi + soff,     ghi + g);
            cp_async16(s_hi + soff + 8, ghi + g + 8);
            cp_async16(s_lo + soff,     glo + g);
            cp_async16(s_lo + soff + 8, glo + g + 8);
        } else {
            uint4 z = make_uint4(0u, 0u, 0u, 0u);
            *(uint4*)(s_hi + soff) = z; *(uint4*)(s_hi + soff + 8) = z;
            *(uint4*)(s_lo + soff) = z; *(uint4*)(s_lo + soff + 8) = z;
        }
    }
    cp_commit();
}

template <int NCT, int ACT, int OUTF32>
__global__ void __launch_bounds__(256, 2)
conv_mma_kernel(const __nv_bfloat16* __restrict__ ghi,
                const __nv_bfloat16* __restrict__ glo,
                const __nv_bfloat16* __restrict__ gwh,
                const __nv_bfloat16* __restrict__ gwl,
                const float* __restrict__ bias,
                __nv_bfloat16* __restrict__ ohi,
                __nv_bfloat16* __restrict__ olo,
                float* __restrict__ of32,
                int H, int W, int CBIN, int COUT, int GRPS)
{
    constexpr int COUTP = NCT * 16;
    constexpr int WPL = 9 * COUTP * 16;
    extern __shared__ char smraw[];
    __nv_bfloat16* base = (__nv_bfloat16*)smraw;
    // layout: [buf0 in_hi|in_lo][buf1 in_hi|in_lo][buf0 wh|wl][buf1 wh|wl]
    __nv_bfloat16* in_b[2]  = { base, base + 2 * IN_PLANE };
    __nv_bfloat16* w_b[2]   = { base + 4 * IN_PLANE, base + 4 * IN_PLANE + 2 * WPL };

    const int bx = blockIdx.x * 32;
    const int by = blockIdx.y * 8;
    const int grp = blockIdx.z % GRPS;
    const int b   = blockIdx.z / GRPS;

    const int tid  = threadIdx.x;
    const int warp = tid >> 5;
    const int lane = tid & 31;
    const int gid  = lane >> 2;   // 0..7
    const int qid  = lane & 3;    // 0..3

    float acc[NCT][4][4];
#pragma unroll
    for (int ct = 0; ct < NCT; ct++)
#pragma unroll
        for (int nt = 0; nt < 4; nt++) {
            acc[ct][nt][0] = 0.f; acc[ct][nt][1] = 0.f;
            acc[ct][nt][2] = 0.f; acc[ct][nt][3] = 0.f;
        }

    // prologue: stage chunk 0
    stage_chunk<NCT>(in_b[0], in_b[0] + IN_PLANE, w_b[0], w_b[0] + WPL,
                     ghi, glo, gwh, gwl, b, grp, 0, CBIN, bx, by, H, W, tid);

#pragma unroll 1
    for (int cb = 0; cb < CBIN; cb++) {
        if (cb + 1 < CBIN) {
            int nb = (cb + 1) & 1;
            stage_chunk<NCT>(in_b[nb], in_b[nb] + IN_PLANE, w_b[nb], w_b[nb] + WPL,
                             ghi, glo, gwh, gwl, b, grp, cb + 1, CBIN, bx, by, H, W, tid);
            asm volatile("cp.async.wait_group 1;");
        } else {
            asm volatile("cp.async.wait_group 0;");
        }
        __syncthreads();

        const int bs = cb & 1;
        const __nv_bfloat16* s_hi = in_b[bs];
        const __nv_bfloat16* s_lo = in_b[bs] + IN_PLANE;
        const __nv_bfloat16* s_wh = w_b[bs];
        const __nv_bfloat16* s_wl = w_b[bs] + WPL;

        int ky = 0, kx = 0;
#pragma unroll 1
        for (int tap = 0; tap < 9; tap++) {
            unsigned ah[NCT][4], al[NCT][4];
            const int wbase = tap * COUTP * 16 + 4 * qid;
#pragma unroll
            for (int ct = 0; ct < NCT; ct++) {
                int co_l = ct * 16 + gid;
                uint2 h0 = *(const uint2*)(s_wh + wbase + co_l * 16);
                uint2 h1 = *(const uint2*)(s_wh + wbase + (co_l + 8) * 16);
                ah[ct][0] = h0.x; ah[ct][2] = h0.y;
                ah[ct][1] = h1.x; ah[ct][3] = h1.y;
                uint2 l0 = *(const uint2*)(s_wl + wbase + co_l * 16);
                uint2 l1 = *(const uint2*)(s_wl + wbase + (co_l + 8) * 16);
                al[ct][0] = l0.x; al[ct][2] = l0.y;
                al[ct][1] = l1.x; al[ct][3] = l1.y;
            }
            const int rowb = warp + ky;
#pragma unroll
            for (int nt = 0; nt < 4; nt++) {
                int colb = nt * 8 + gid + kx;
                int ibase = (rowb * C_PITCH + colb) * 16 + 4 * qid;
                uint2 bh = *(const uint2*)(s_hi + ibase);
                uint2 bl = *(const uint2*)(s_lo + ibase);
#pragma unroll
                for (int ct = 0; ct < NCT; ct++) {
                    mma16816(acc[ct][nt], ah[ct], bh.x, bh.y);
                    mma16816(acc[ct][nt], ah[ct], bl.x, bl.y);
                    mma16816(acc[ct][nt], al[ct], bh.x, bh.y);
                }
            }
            if (++kx == 3) { kx = 0; ++ky; }
        }
        __syncthreads();
    }

    // ---- epilogue ----
    const int gy = by + warp;
    if (OUTF32) {
#pragma unroll
        for (int ct = 0; ct < NCT; ct++) {
            int co0r = grp * COUTP + ct * 16 + gid;
            int co1r = co0r + 8;
            bool ok0 = co0r < COUT;
            bool ok1 = co1r < COUT;
            float bv0 = ok0 ? bias[co0r] : 0.f;
            float bv1 = ok1 ? bias[co1r] : 0.f;
#pragma unroll
            for (int nt = 0; nt < 4; nt++) {
                int gxv = bx + nt * 8 + 2 * qid;
                if (ok0) {
                    float v0 = tanhf(acc[ct][nt][0] + bv0);
                    float v1 = tanhf(acc[ct][nt][1] + bv0);
                    *(float2*)&of32[((size_t)(b * COUT + co0r) * H + gy) * W + gxv]
                        = make_float2(v0, v1);
                }
                if (ok1) {
                    float v0 = tanhf(acc[ct][nt][2] + bv1);
                    float v1 = tanhf(acc[ct][nt][3] + bv1);
                    *(float2*)&of32[((size_t)(b * COUT + co1r) * H + gy) * W + gxv]
                        = make_float2(v0, v1);
                }
            }
        }
    } else {
        const int nCBo = COUT >> 4;
        const int slot0 = pos16(gid);
        const int slot1 = slot0 + 2;
#pragma unroll
        for (int ct = 0; ct < NCT; ct++) {
            int co_g = grp * COUTP + ct * 16 + gid;
            int cbo = co_g >> 4;
            float bv0 = bias[co_g];
            float bv1 = bias[co_g + 8];
#pragma unroll
            for (int nt = 0; nt < 4; nt++) {
                int gxv = bx + nt * 8 + 2 * qid;
                size_t g = ((((size_t)b * nCBo + cbo) * H + gy) * W + gxv) << 4;
                float v0 = acc[ct][nt][0] + bv0;
                float v1 = acc[ct][nt][1] + bv0;
                float v2 = acc[ct][nt][2] + bv1;
                float v3 = acc[ct][nt][3] + bv1;
                if (ACT == 1) {
                    v0 = fmaxf(v0, 0.f); v1 = fmaxf(v1, 0.f);
                    v2 = fmaxf(v2, 0.f); v3 = fmaxf(v3, 0.f);
                }
                __nv_bfloat16 h, l;
                bf16split(v0, h, l); ohi[g + slot0]      = h; olo[g + slot0]      = l;
                bf16split(v1, h, l); ohi[g + 16 + slot0] = h; olo[g + 16 + slot0] = l;
                bf16split(v2, h, l); ohi[g + slot1]      = h; olo[g + slot1]      = l;
                bf16split(v3, h, l); ohi[g + 16 + slot1] = h; olo[g + 16 + slot1] = l;
            }
        }
    }
}

// ---------------------------------------------------------------------------
// MaxPool 2x2 stride 2 on bf16 hi/lo act layout (slot-preserving)
// ---------------------------------------------------------------------------
__global__ void pool_bf16(const __nv_bfloat16* __restrict__ ihi,
                          const __nv_bfloat16* __restrict__ ilo,
                          __nv_bfloat16* __restrict__ ohi,
                          __nv_bfloat16* __restrict__ olo,
                          int total, int Hout, int Wout)
{
    int idx = blockIdx.x * blockDim.x + threadIdx.x;
    if (idx >= total) return;
    int slot = idx & 15;
    int p = idx >> 4;
    int x = p % Wout;
    int t = p / Wout;
    int y = t % Hout;
    int c = t / Hout;
    int Win = 2 * Wout;
    size_t base = (((size_t)c * 2 * Hout + 2 * y) * Win + 2 * x) * 16 + slot;
    size_t o00 = base, o01 = base + 16;
    size_t o10 = base + (size_t)Win * 16, o11 = o10 + 16;
    float v00 = __bfloat162float(ihi[o00]) + __bfloat162float(ilo[o00]);
    float v01 = __bfloat162float(ihi[o01]) + __bfloat162float(ilo[o01]);
    float v10 = __bfloat162float(ihi[o10]) + __bfloat162float(ilo[o10]);
    float v11 = __bfloat162float(ihi[o11]) + __bfloat162float(ilo[o11]);
    size_t best = o00; float bv = v00;
    if (v01 > bv) { bv = v01; best = o01; }
    if (v10 > bv) { bv = v10; best = o10; }
    if (v11 > bv) { bv = v11; best = o11; }
    ohi[idx] = ihi[best];
    olo[idx] = ilo[best];
}

// ---------------------------------------------------------------------------
// Bilinear upsample x2 on bf16 hi/lo act layout (slot-preserving)
// ---------------------------------------------------------------------------
__global__ void up_bf16(const __nv_bfloat16* __restrict__ ihi,
                        const __nv_bfloat16* __restrict__ ilo,
                        __nv_bfloat16* __restrict__ ohi,
                        __nv_bfloat16* __restrict__ olo,
                        int total, int Hin, int Win)
{
    int idx = blockIdx.x * blockDim.x + threadIdx.x;
    if (idx >= total) return;
    int slot = idx & 15;
    int p = idx >> 4;
    int Hout = 2 * Hin, Wout = 2 * Win;
    int ox = p % Wout;
    int t = p / Wout;
    int oy = t % Hout;
    int c = t / Hout;

    float fy = (oy + 0.5f) * 0.5f - 0.5f;
    float fx = (ox + 0.5f) * 0.5f - 0.5f;
    int y0 = (int)floorf(fy);
    int x0 = (int)floorf(fx);
    float wy = fy - (float)y0;
    float wx = fx - (float)x0;
    int y0c = max(y0, 0), y1c = min(y0 + 1, Hin - 1);
    int x0c = max(x0, 0), x1c = min(x0 + 1, Win - 1);

    size_t cb = (size_t)c * Hin;
    size_t o00 = ((cb + y0c) * Win + x0c) * 16 + slot;
    size_t o01 = ((cb + y0c) * Win + x1c) * 16 + slot;
    size_t o10 = ((cb + y1c) * Win + x0c) * 16 + slot;
    size_t o11 = ((cb + y1c) * Win + x1c) * 16 + slot;
    float v00 = __bfloat162float(ihi[o00]) + __bfloat162float(ilo[o00]);
    float v01 = __bfloat162float(ihi[o01]) + __bfloat162float(ilo[o01]);
    float v10 = __bfloat162float(ihi[o10]) + __bfloat162float(ilo[o10]);
    float v11 = __bfloat162float(ihi[o11]) + __bfloat162float(ilo[o11]);
    float v = (1.f - wy) * ((1.f - wx) * v00 + wx * v01)
            +        wy  * ((1.f - wx) * v10 + wx * v11);
    __nv_bfloat16 h, l;
    bf16split(v, h, l);
    ohi[idx] = h;
    olo[idx] = l;
}

// ---------------------------------------------------------------------------
// deformed = base_grid + flow^T * temp
// ---------------------------------------------------------------------------
__global__ void deform_kernel(const float* __restrict__ flow,
                              const float* __restrict__ temp,
                              float* __restrict__ def)
{
    int idx = blockIdx.x * blockDim.x + threadIdx.x;
    int total = BATCH * IMG_H * IMG_W;
    if (idx >= total) return;
    int w = idx % IMG_W;
    int h = (idx / IMG_W) % IMG_H;
    int b = idx / (IMG_W * IMG_H);
    float gx = -1.0f + 2.0f * (float)w / (float)(IMG_W - 1);
    float gy = -1.0f + 2.0f * (float)h / (float)(IMG_H - 1);
    float t = temp[0];
    float fx = flow[((size_t)(b * 2 + 0) * IMG_H + h) * IMG_W + w];
    float fy = flow[((size_t)(b * 2 + 1) * IMG_H + h) * IMG_W + w];
    def[(size_t)idx * 2 + 0] = gx + fx * t;
    def[(size_t)idx * 2 + 1] = gy + fy * t;
}

// ---------------------------------------------------------------------------
// Patch extraction (grid_sample bilinear, zeros padding)
// ---------------------------------------------------------------------------
__global__ void patches_kernel(const float* __restrict__ x,
                               const float* __restrict__ def,
                               float* __restrict__ out)
{
    int bn = blockIdx.x;
    int b = bn >> 8;
    int n = bn & 255;
    int hy = n >> 4;
    int wx = n & 15;
    const float* dptr = def + (((size_t)(b * IMG_H + hy * STRIDE_) * IMG_W) + wx * STRIDE_) * 2;
    float cx = dptr[0];
    float cy = dptr[1];

    for (int p = threadIdx.x; p < PATCH * PATCH; p += blockDim.x) {
        int i = p >> 6;
        int j = p & 63;
        float pxv = -1.0f + 2.0f * (float)j / (float)(PATCH - 1);
        float pyv = -1.0f + 2.0f * (float)i / (float)(PATCH - 1);
        float gx = cx + pxv * ((float)PATCH / (float)IMG_W);
        float gy = cy + pyv * ((float)PATCH / (float)IMG_H);
        float ix = ((gx + 1.0f) * (float)IMG_W - 1.0f) * 0.5f;
        float iy = ((gy + 1.0f) * (float)IMG_H - 1.0f) * 0.5f;
        float x0f = floorf(ix), y0f = floorf(iy);
        float wx1 = ix - x0f, wy1 = iy - y0f;
        int x0 = (int)x0f, y0 = (int)y0f;
        int x1 = x0 + 1, y1 = y0 + 1;
        bool vx0 = (x0 >= 0) & (x0 <= IMG_W - 1);
        bool vx1 = (x1 >= 0) & (x1 <= IMG_W - 1);
        bool vy0 = (y0 >= 0) & (y0 <= IMG_H - 1);
        bool vy1 = (y1 >= 0) & (y1 <= IMG_H - 1);
        int x0c = min(max(x0, 0), IMG_W - 1);
        int x1c = min(max(x1, 0), IMG_W - 1);
        int y0c = min(max(y0, 0), IMG_H - 1);
        int y1c = min(max(y1, 0), IMG_H - 1);
        float w00 = (1.f - wx1) * (1.f - wy1) * (float)(vx0 && vy0);
        float w10 = wx1 * (1.f - wy1) * (float)(vx1 && vy0);
        float w01 = (1.f - wx1) * wy1 * (float)(vx0 && vy1);
        float w11 = wx1 * wy1 * (float)(vx1 && vy1);

#pragma unroll
        for (int c = 0; c < 3; c++) {
            const float* img = x + (size_t)(b * 3 + c) * IMG_H * IMG_W;
            float v = img[y0c * IMG_W + x0c] * w00
                    + img[y0c * IMG_W + x1c] * w10
                    + img[y1c * IMG_W + x0c] * w01
                    + img[y1c * IMG_W + x1c] * w11;
            out[((size_t)(bn)*3 + c) * (PATCH * PATCH) + p] = v;
        }
    }
}

// ---------------------------------------------------------------------------
// Launch
// ---------------------------------------------------------------------------
#define SMEM_NCT2 ((4 * IN_PLANE + 4 * 4608) * 2)   // 82,944 B
#define SMEM_NCT1 ((4 * IN_PLANE + 4 * 2304) * 2)   // 64,512 B

extern "C" void kernel_launch(void* const* d_in, const int* in_sizes, int n_in,
                              void* d_out, int out_size)
{
    const float* x  = (const float*)d_in[0];
    const float* w0 = (const float*)d_in[1];  const float* b0 = (const float*)d_in[2];
    const float* w1 = (const float*)d_in[3];  const float* b1 = (const float*)d_in[4];
    const float* w2 = (const float*)d_in[5];  const float* b2 = (const float*)d_in[6];
    const float* w3 = (const float*)d_in[7];  const float* b3 = (const float*)d_in[8];
    const float* w4 = (const float*)d_in[9];  const float* b4 = (const float*)d_in[10];
    const float* w5 = (const float*)d_in[11]; const float* b5 = (const float*)d_in[12];
    const float* w6 = (const float*)d_in[13]; const float* b6 = (const float*)d_in[14];
    const float* w7 = (const float*)d_in[15]; const float* b7 = (const float*)d_in[16];
    const float* temp = (const float*)d_in[17];

    float* out     = (float*)d_out;
    float* patches = out;
    float* flow    = out + PATCHES_ELEMS;
    float* def     = out + PATCHES_ELEMS + FLOW_ELEMS;

    float* A;  cudaGetSymbolAddress((void**)&A, g_bufA);
    float* Bb; cudaGetSymbolAddress((void**)&Bb, g_bufB);
    __nv_bfloat16* WH; cudaGetSymbolAddress((void**)&WH, g_wh);
    __nv_bfloat16* WL; cudaGetSymbolAddress((void**)&WL, g_wl);

    __nv_bfloat16* Ahi = (__nv_bfloat16*)A;
    __nv_bfloat16* Alo = Ahi + PLANE_ELEMS;
    __nv_bfloat16* Bhi = (__nv_bfloat16*)Bb;
    __nv_bfloat16* Blo = Bhi + PLANE_ELEMS;

    cudaFuncSetAttribute((const void*)conv_mma_kernel<2, 1, 0>,
                         cudaFuncAttributeMaxDynamicSharedMemorySize, SMEM_NCT2);
    cudaFuncSetAttribute((const void*)conv_mma_kernel<1, 2, 1>,
                         cudaFuncAttributeMaxDynamicSharedMemorySize, SMEM_NCT1);

    // ---- preconvert weights ----
    struct { const float* w; int off, COUT, CIN, COUTP, GRPS, CBLKS; } wl[8] = {
        {w0, 0,      32,  3, 32, 1, 1},
        {w1, 4608,   32, 32, 32, 1, 2},
        {w2, 13824,  64, 32, 32, 2, 2},
        {w3, 32256,  64, 64, 32, 2, 4},
        {w4, 69120,  64, 64, 32, 2, 4},
        {w5, 105984, 32, 64, 32, 1, 4},
        {w6, 124416, 32, 32, 32, 1, 2},
        {w7, 133632,  2, 32, 16, 1, 2},
    };
    for (int i = 0; i < 8; i++) {
        int total = wl[i].GRPS * wl[i].CBLKS * 9 * wl[i].COUTP * 16;
        wconv_kernel<<<(total + 255) / 256, 256>>>(
            wl[i].w, WH + wl[i].off, WL + wl[i].off,
            wl[i].COUT, wl[i].CIN, wl[i].COUTP, wl[i].GRPS, wl[i].CBLKS);
    }

    // ---- x -> bf16 act layout (B) ----
    {
        int total = BATCH * IMG_H * IMG_W * 16;
        xcvt_kernel<<<(total + 255) / 256, 256>>>(x, Bhi, Blo);
    }

    // ---- flow net (ping-pong B <-> A) ----
    // conv0: 3->32 @512 relu  (B -> A)
    conv_mma_kernel<2, 1, 0><<<dim3(16, 64, 4), 256, SMEM_NCT2>>>(
        Bhi, Blo, WH + 0, WL + 0, b0, Ahi, Alo, nullptr, 512, 512, 1, 32, 1);
    // conv1: 32->32 @512 relu (A -> B)
    conv_mma_kernel<2, 1, 0><<<dim3(16, 64, 4), 256, SMEM_NCT2>>>(
        Ahi, Alo, WH + 4608, WL + 4608, b1, Bhi, Blo, nullptr, 512, 512, 2, 32, 1);
    // pool: 512->256          (B -> A)
    {
        int total = BATCH * 2 * 256 * 256 * 16;
        pool_bf16<<<(total + 255) / 256, 256>>>(Bhi, Blo, Ahi, Alo, total, 256, 256);
    }
    // conv2: 32->64 @256 relu (A -> B)
    conv_mma_kernel<2, 1, 0><<<dim3(8, 32, 4 * 2), 256, SMEM_NCT2>>>(
        Ahi, Alo, WH + 13824, WL + 13824, b2, Bhi, Blo, nullptr, 256, 256, 2, 64, 2);
    // conv3: 64->64 @256 relu (B -> A)
    conv_mma_kernel<2, 1, 0><<<dim3(8, 32, 4 * 2), 256, SMEM_NCT2>>>(
        Bhi, Blo, WH + 32256, WL + 32256, b3, Ahi, Alo, nullptr, 256, 256, 4, 64, 2);
    // pool: 256->128          (A -> B)
    {
        int total = BATCH * 4 * 128 * 128 * 16;
        pool_bf16<<<(total + 255) / 256, 256>>>(Ahi, Alo, Bhi, Blo, total, 128, 128);
    }
    // up: 128->256            (B -> A)
    {
        int total = BATCH * 4 * 256 * 256 * 16;
        up_bf16<<<(total + 255) / 256, 256>>>(Bhi, Blo, Ahi, Alo, total, 128, 128);
    }
    // conv4: 64->64 @256 relu (A -> B)
    conv_mma_kernel<2, 1, 0><<<dim3(8, 32, 4 * 2), 256, SMEM_NCT2>>>(
        Ahi, Alo, WH + 69120, WL + 69120, b4, Bhi, Blo, nullptr, 256, 256, 4, 64, 2);
    // conv5: 64->32 @256 relu (B -> A)
    conv_mma_kernel<2, 1, 0><<<dim3(8, 32, 4), 256, SMEM_NCT2>>>(
        Bhi, Blo, WH + 105984, WL + 105984, b5, Ahi, Alo, nullptr, 256, 256, 4, 32, 1);
    // up: 256->512            (A -> B)
    {
        int total = BATCH * 2 * 512 * 512 * 16;
        up_bf16<<<(total + 255) / 256, 256>>>(Ahi, Alo, Bhi, Blo, total, 256, 256);
    }
    // conv6: 32->32 @512 relu (B -> A)
    conv_mma_kernel<2, 1, 0><<<dim3(16, 64, 4), 256, SMEM_NCT2>>>(
        Bhi, Blo, WH + 124416, WL + 124416, b6, Ahi, Alo, nullptr, 512, 512, 2, 32, 1);
    // conv7: 32->2 @512 tanh  (A -> flow, fp32)
    conv_mma_kernel<1, 2, 1><<<dim3(16, 64, 4), 256, SMEM_NCT1>>>(
        Ahi, Alo, WH + 133632, WL + 133632, b7, nullptr, nullptr, flow, 512, 512, 2, 2, 1);

    // deformed grid
    {
        int total = BATCH * IMG_H * IMG_W;
        deform_kernel<<<(total + 255) / 256, 256>>>(flow, temp, def);
    }
    // patches
    patches_kernel<<<dim3(BATCH * NPATCH), 256>>>(x, def, patches);
}

// round 10
// speedup vs baseline: 1.1188x; 1.1188x over previous
#include <cuda_runtime.h>
#include <cuda_bf16.h>
#include <math.h>

// ---------------------------------------------------------------------------
// Problem constants
// ---------------------------------------------------------------------------
#define BATCH 4
#define IMG_H 512
#define IMG_W 512
#define PATCH 64
#define STRIDE_ 32
#define NPATCH 256
#define PATCHES_ELEMS (BATCH * NPATCH * 3 * PATCH * PATCH)   // 12,582,912
#define FLOW_ELEMS    (BATCH * 2 * IMG_H * IMG_W)            //  2,097,152

// Scratch (device globals). Each 33.5M floats = 67.1M bf16 = hi+lo planes.
__device__ __align__(256) float g_bufA[33554432];
__device__ __align__(256) float g_bufB[33554432];
#define PLANE_ELEMS 33554432

// Preconverted weights (bf16 hi/lo, pos16-permuted).
#define WSCRATCH 138240
__device__ __align__(256) __nv_bfloat16 g_wh[WSCRATCH];
__device__ __align__(256) __nv_bfloat16 g_wl[WSCRATCH];

// ---------------------------------------------------------------------------
// helpers
// ---------------------------------------------------------------------------
__device__ __forceinline__ void cp_async16(void* smem_dst, const void* gptr) {
    unsigned sa = (unsigned)__cvta_generic_to_shared(smem_dst);
    asm volatile("cp.async.cg.shared.global [%0], [%1], 16;" :: "r"(sa), "l"(gptr));
}
__device__ __forceinline__ void cp_commit() { asm volatile("cp.async.commit_group;"); }
__device__ __forceinline__ void cp_wait0()  { asm volatile("cp.async.wait_group 0;"); }

__device__ __forceinline__ void mma16816(float* c, const unsigned* a, unsigned b0, unsigned b1) {
    asm volatile(
        "mma.sync.aligned.m16n8k16.row.col.f32.bf16.bf16.f32 "
        "{%0,%1,%2,%3}, {%4,%5,%6,%7}, {%8,%9}, {%0,%1,%2,%3};"
        : "+f"(c[0]), "+f"(c[1]), "+f"(c[2]), "+f"(c[3])
        : "r"(a[0]), "r"(a[1]), "r"(a[2]), "r"(a[3]), "r"(b0), "r"(b1));
}

// pos16(2q)=4q, pos16(2q+1)=4q+1, pos16(2q+8)=4q+2, pos16(2q+9)=4q+3 (q=0..3)
__device__ __forceinline__ int pos16(int ci) {
    return (((ci >> 1) & 3) << 2) + (((ci >> 3) & 1) << 1) + (ci & 1);
}
__device__ __forceinline__ void bf16split(float v, __nv_bfloat16& h, __nv_bfloat16& l) {
    h = __float2bfloat16(v);
    l = __float2bfloat16(v - __bfloat162float(h));
}

// ---------------------------------------------------------------------------
// Fused weight preconversion for ALL 8 layers in one launch.
// Layout per layer: [cb][tap][co(COUTP)][pos16(ci)] (GRPS=1 everywhere).
// ---------------------------------------------------------------------------
__constant__ int c_woffs[9]  = {0, 4608, 13824, 32256, 69120, 105984, 124416, 133632, 138240};
__constant__ int c_wCOUT[8]  = {32, 32, 64, 64, 64, 32, 32, 2};
__constant__ int c_wCIN[8]   = {3, 32, 32, 64, 64, 64, 32, 32};
__constant__ int c_wCOUTP[8] = {32, 32, 64, 64, 64, 32, 32, 16};

__global__ void wconv_all(const float* __restrict__ w0, const float* __restrict__ w1,
                          const float* __restrict__ w2, const float* __restrict__ w3,
                          const float* __restrict__ w4, const float* __restrict__ w5,
                          const float* __restrict__ w6, const float* __restrict__ w7,
                          __nv_bfloat16* __restrict__ dh, __nv_bfloat16* __restrict__ dl)
{
    int idx = blockIdx.x * blockDim.x + threadIdx.x;
    if (idx >= WSCRATCH) return;
    int l = 0;
    while (idx >= c_woffs[l + 1]) l++;
    int rel = idx - c_woffs[l];
    int COUT = c_wCOUT[l], CIN = c_wCIN[l], COUTP = c_wCOUTP[l];
    int ci = rel & 15;
    int t = rel >> 4;
    int co = t % COUTP;  t /= COUTP;
    int tap = t % 9;
    int cb = t / 9;
    const float* w;
    switch (l) {
        case 0: w = w0; break; case 1: w = w1; break;
        case 2: w = w2; break; case 3: w = w3; break;
        case 4: w = w4; break; case 5: w = w5; break;
        case 6: w = w6; break; default: w = w7; break;
    }
    int ci_g = cb * 16 + ci;
    float v = 0.f;
    if (co < COUT && ci_g < CIN)
        v = w[((size_t)co * CIN + ci_g) * 9 + tap];
    __nv_bfloat16 h, lo;
    bf16split(v, h, lo);
    int base = idx & ~15;
    dh[base + pos16(ci)] = h;
    dl[base + pos16(ci)] = lo;
}

// ---------------------------------------------------------------------------
// x (fp32 NCHW, C=3) -> act layout [b][cb=0][y][x][pos16(ci)], ci>=3 zero
// ---------------------------------------------------------------------------
__global__ void xcvt_kernel(const float* __restrict__ x,
                            __nv_bfloat16* __restrict__ ohi,
                            __nv_bfloat16* __restrict__ olo)
{
    int idx = blockIdx.x * blockDim.x + threadIdx.x;
    int total = BATCH * IMG_H * IMG_W * 16;
    if (idx >= total) return;
    int ci = idx & 15;
    int p = idx >> 4;
    int xx = p % IMG_W;
    int yy = (p / IMG_W) % IMG_H;
    int b  = p / (IMG_W * IMG_H);
    float v = 0.f;
    if (ci < 3)
        v = x[((size_t)(b * 3 + ci) * IMG_H + yy) * IMG_W + xx];
    __nv_bfloat16 h, l;
    bf16split(v, h, l);
    size_t o = ((size_t)p << 4) + pos16(ci);
    ohi[o] = h;
    olo[o] = l;
}

// ---------------------------------------------------------------------------
// Implicit-GEMM 3x3 conv via mma.sync bf16 (3-term hi/lo split).
// Tile: (NT*8) wide x 8 tall x (NCT*16) couts. 256 threads (8 warps).
// Single-buffered cp.async staging (R8 structure; occ 2 overlaps waits).
// OUTF32=0: write bf16 hi/lo act layout (ACT=relu).  OUTF32=1: fp32 NCHW+tanh.
// ---------------------------------------------------------------------------
template <int NCT, int NT, int ACT, int OUTF32>
__global__ void __launch_bounds__(256, 2)
conv_mma_kernel(const __nv_bfloat16* __restrict__ ghi,
                const __nv_bfloat16* __restrict__ glo,
                const __nv_bfloat16* __restrict__ gwh,
                const __nv_bfloat16* __restrict__ gwl,
                const float* __restrict__ bias,
                __nv_bfloat16* __restrict__ ohi,
                __nv_bfloat16* __restrict__ olo,
                float* __restrict__ of32,
                int H, int W, int CBIN, int COUT, int GRPS)
{
    constexpr int COUTP = NCT * 16;
    constexpr int TILEW = NT * 8;
    constexpr int PITCH = TILEW + 4;
    constexpr int IN_PLANE = 10 * PITCH * 16;
    constexpr int WPL = 9 * COUTP * 16;
    extern __shared__ char smraw[];
    __nv_bfloat16* s_hi = (__nv_bfloat16*)smraw;
    __nv_bfloat16* s_lo = s_hi + IN_PLANE;
    __nv_bfloat16* s_wh = s_hi + 2 * IN_PLANE;
    __nv_bfloat16* s_wl = s_wh + WPL;

    const int bx = blockIdx.x * TILEW;
    const int by = blockIdx.y * 8;
    const int grp = blockIdx.z % GRPS;
    const int b   = blockIdx.z / GRPS;

    const int tid  = threadIdx.x;
    const int warp = tid >> 5;
    const int lane = tid & 31;
    const int gid  = lane >> 2;   // 0..7
    const int qid  = lane & 3;    // 0..3

    float acc[NCT][NT][4];
#pragma unroll
    for (int ct = 0; ct < NCT; ct++)
#pragma unroll
        for (int nt = 0; nt < NT; nt++) {
            acc[ct][nt][0] = 0.f; acc[ct][nt][1] = 0.f;
            acc[ct][nt][2] = 0.f; acc[ct][nt][3] = 0.f;
        }

    for (int cb = 0; cb < CBIN; cb++) {
        __syncthreads();
        // ---- stage weights (raw bf16 copy) ----
        {
            const __nv_bfloat16* pwh = gwh + ((size_t)grp * CBIN + cb) * WPL;
            const __nv_bfloat16* pwl = gwl + ((size_t)grp * CBIN + cb) * WPL;
            for (int idx = tid * 8; idx < WPL; idx += 2048) {
                cp_async16(s_wh + idx, pwh + idx);
                cp_async16(s_wl + idx, pwl + idx);
            }
        }
        // ---- stage input chunk: 10 x (TILEW+2) pixels, 32B/pixel/plane ----
        for (int p = tid; p < 10 * (TILEW + 2); p += 256) {
            int row = p / (TILEW + 2);
            int col = p - row * (TILEW + 2);
            int gy = by + row - 1;
            int gx = bx + col - 1;
            int soff = (row * PITCH + col) * 16;
            if (gy >= 0 && gy < H && gx >= 0 && gx < W) {
                size_t g = ((((size_t)b * CBIN + cb) * H + gy) * W + gx) << 4;
                cp_async16(s_hi + soff,     ghi + g);
                cp_async16(s_hi + soff + 8, ghi + g + 8);
                cp_async16(s_lo + soff,     glo + g);
                cp_async16(s_lo + soff + 8, glo + g + 8);
            } else {
                uint4 z = make_uint4(0u, 0u, 0u, 0u);
                *(uint4*)(s_hi + soff) = z; *(uint4*)(s_hi + soff + 8) = z;
                *(uint4*)(s_lo + soff) = z; *(uint4*)(s_lo + soff + 8) = z;
            }
        }
        cp_commit();
        cp_wait0();
        __syncthreads();

        // ---- compute: 9 taps ----
        int ky = 0, kx = 0;
#pragma unroll 1
        for (int tap = 0; tap < 9; tap++) {
            unsigned ah[NCT][4], al[NCT][4];
            const int wbase = tap * COUTP * 16 + 4 * qid;
#pragma unroll
            for (int ct = 0; ct < NCT; ct++) {
                int co_l = ct * 16 + gid;
                uint2 h0 = *(const uint2*)(s_wh + wbase + co_l * 16);
                uint2 h1 = *(const uint2*)(s_wh + wbase + (co_l + 8) * 16);
                ah[ct][0] = h0.x; ah[ct][2] = h0.y;
                ah[ct][1] = h1.x; ah[ct][3] = h1.y;
                uint2 l0 = *(const uint2*)(s_wl + wbase + co_l * 16);
                uint2 l1 = *(const uint2*)(s_wl + wbase + (co_l + 8) * 16);
                al[ct][0] = l0.x; al[ct][2] = l0.y;
                al[ct][1] = l1.x; al[ct][3] = l1.y;
            }
            const int rowb = warp + ky;
#pragma unroll
            for (int nt = 0; nt < NT; nt++) {
                int colb = nt * 8 + gid + kx;
                int ibase = (rowb * PITCH + colb) * 16 + 4 * qid;
                uint2 bh = *(const uint2*)(s_hi + ibase);
                uint2 bl = *(const uint2*)(s_lo + ibase);
#pragma unroll
                for (int ct = 0; ct < NCT; ct++) {
                    mma16816(acc[ct][nt], ah[ct], bh.x, bh.y);
                    mma16816(acc[ct][nt], ah[ct], bl.x, bl.y);
                    mma16816(acc[ct][nt], al[ct], bh.x, bh.y);
                }
            }
            if (++kx == 3) { kx = 0; ++ky; }
        }
    }

    // ---- epilogue ----
    const int gy = by + warp;
    if (OUTF32) {
#pragma unroll
        for (int ct = 0; ct < NCT; ct++) {
            int co0r = grp * COUTP + ct * 16 + gid;
            int co1r = co0r + 8;
            bool ok0 = co0r < COUT;
            bool ok1 = co1r < COUT;
            float bv0 = ok0 ? bias[co0r] : 0.f;
            float bv1 = ok1 ? bias[co1r] : 0.f;
#pragma unroll
            for (int nt = 0; nt < NT; nt++) {
                int gxv = bx + nt * 8 + 2 * qid;
                if (ok0) {
                    float v0 = tanhf(acc[ct][nt][0] + bv0);
                    float v1 = tanhf(acc[ct][nt][1] + bv0);
                    *(float2*)&of32[((size_t)(b * COUT + co0r) * H + gy) * W + gxv]
                        = make_float2(v0, v1);
                }
                if (ok1) {
                    float v0 = tanhf(acc[ct][nt][2] + bv1);
                    float v1 = tanhf(acc[ct][nt][3] + bv1);
                    *(float2*)&of32[((size_t)(b * COUT + co1r) * H + gy) * W + gxv]
                        = make_float2(v0, v1);
                }
            }
        }
    } else {
        const int nCBo = COUT >> 4;
        const int slot0 = pos16(gid);
        const int slot1 = slot0 + 2;
#pragma unroll
        for (int ct = 0; ct < NCT; ct++) {
            int co_g = grp * COUTP + ct * 16 + gid;
            int cbo = co_g >> 4;
            float bv0 = bias[co_g];
            float bv1 = bias[co_g + 8];
#pragma unroll
            for (int nt = 0; nt < NT; nt++) {
                int gxv = bx + nt * 8 + 2 * qid;
                size_t g = ((((size_t)b * nCBo + cbo) * H + gy) * W + gxv) << 4;
                float v0 = acc[ct][nt][0] + bv0;
                float v1 = acc[ct][nt][1] + bv0;
                float v2 = acc[ct][nt][2] + bv1;
                float v3 = acc[ct][nt][3] + bv1;
                if (ACT == 1) {
                    v0 = fmaxf(v0, 0.f); v1 = fmaxf(v1, 0.f);
                    v2 = fmaxf(v2, 0.f); v3 = fmaxf(v3, 0.f);
                }
                __nv_bfloat16 h, l;
                bf16split(v0, h, l); ohi[g + slot0]      = h; olo[g + slot0]      = l;
                bf16split(v1, h, l); ohi[g + 16 + slot0] = h; olo[g + 16 + slot0] = l;
                bf16split(v2, h, l); ohi[g + slot1]      = h; olo[g + slot1]      = l;
                bf16split(v3, h, l); ohi[g + 16 + slot1] = h; olo[g + 16 + slot1] = l;
            }
        }
    }
}

// ---------------------------------------------------------------------------
// MaxPool 2x2 stride 2 on bf16 hi/lo act layout (slot-preserving)
// ---------------------------------------------------------------------------
__global__ void pool_bf16(const __nv_bfloat16* __restrict__ ihi,
                          const __nv_bfloat16* __restrict__ ilo,
                          __nv_bfloat16* __restrict__ ohi,
                          __nv_bfloat16* __restrict__ olo,
                          int total, int Hout, int Wout)
{
    int idx = blockIdx.x * blockDim.x + threadIdx.x;
    if (idx >= total) return;
    int slot = idx & 15;
    int p = idx >> 4;
    int x = p % Wout;
    int t = p / Wout;
    int y = t % Hout;
    int c = t / Hout;
    int Win = 2 * Wout;
    size_t base = (((size_t)c * 2 * Hout + 2 * y) * Win + 2 * x) * 16 + slot;
    size_t o00 = base, o01 = base + 16;
    size_t o10 = base + (size_t)Win * 16, o11 = o10 + 16;
    float v00 = __bfloat162float(ihi[o00]) + __bfloat162float(ilo[o00]);
    float v01 = __bfloat162float(ihi[o01]) + __bfloat162float(ilo[o01]);
    float v10 = __bfloat162float(ihi[o10]) + __bfloat162float(ilo[o10]);
    float v11 = __bfloat162float(ihi[o11]) + __bfloat162float(ilo[o11]);
    size_t best = o00; float bv = v00;
    if (v01 > bv) { bv = v01; best = o01; }
    if (v10 > bv) { bv = v10; best = o10; }
    if (v11 > bv) { bv = v11; best = o11; }
    ohi[idx] = ihi[best];
    olo[idx] = ilo[best];
}

// ---------------------------------------------------------------------------
// Bilinear upsample x2 on bf16 hi/lo act layout (slot-preserving)
// ---------------------------------------------------------------------------
__global__ void up_bf16(const __nv_bfloat16* __restrict__ ihi,
                        const __nv_bfloat16* __restrict__ ilo,
                        __nv_bfloat16* __restrict__ ohi,
                        __nv_bfloat16* __restrict__ olo,
                        int total, int Hin, int Win)
{
    int idx = blockIdx.x * blockDim.x + threadIdx.x;
    if (idx >= total) return;
    int slot = idx & 15;
    int p = idx >> 4;
    int Hout = 2 * Hin, Wout = 2 * Win;
    int ox = p % Wout;
    int t = p / Wout;
    int oy = t % Hout;
    int c = t / Hout;

    float fy = (oy + 0.5f) * 0.5f - 0.5f;
    float fx = (ox + 0.5f) * 0.5f - 0.5f;
    int y0 = (int)floorf(fy);
    int x0 = (int)floorf(fx);
    float wy = fy - (float)y0;
    float wx = fx - (float)x0;
    int y0c = max(y0, 0), y1c = min(y0 + 1, Hin - 1);
    int x0c = max(x0, 0), x1c = min(x0 + 1, Win - 1);

    size_t cb = (size_t)c * Hin;
    size_t o00 = ((cb + y0c) * Win + x0c) * 16 + slot;
    size_t o01 = ((cb + y0c) * Win + x1c) * 16 + slot;
    size_t o10 = ((cb + y1c) * Win + x0c) * 16 + slot;
    size_t o11 = ((cb + y1c) * Win + x1c) * 16 + slot;
    float v00 = __bfloat162float(ihi[o00]) + __bfloat162float(ilo[o00]);
    float v01 = __bfloat162float(ihi[o01]) + __bfloat162float(ilo[o01]);
    float v10 = __bfloat162float(ihi[o10]) + __bfloat162float(ilo[o10]);
    float v11 = __bfloat162float(ihi[o11]) + __bfloat162float(ilo[o11]);
    float v = (1.f - wy) * ((1.f - wx) * v00 + wx * v01)
            +        wy  * ((1.f - wx) * v10 + wx * v11);
    __nv_bfloat16 h, l;
    bf16split(v, h, l);
    ohi[idx] = h;
    olo[idx] = l;
}

// ---------------------------------------------------------------------------
// deformed = base_grid + flow^T * temp
// ---------------------------------------------------------------------------
__global__ void deform_kernel(const float* __restrict__ flow,
                              const float* __restrict__ temp,
                              float* __restrict__ def)
{
    int idx = blockIdx.x * blockDim.x + threadIdx.x;
    int total = BATCH * IMG_H * IMG_W;
    if (idx >= total) return;
    int w = idx % IMG_W;
    int h = (idx / IMG_W) % IMG_H;
    int b = idx / (IMG_W * IMG_H);
    float gx = -1.0f + 2.0f * (float)w / (float)(IMG_W - 1);
    float gy = -1.0f + 2.0f * (float)h / (float)(IMG_H - 1);
    float t = temp[0];
    float fx = flow[((size_t)(b * 2 + 0) * IMG_H + h) * IMG_W + w];
    float fy = flow[((size_t)(b * 2 + 1) * IMG_H + h) * IMG_W + w];
    def[(size_t)idx * 2 + 0] = gx + fx * t;
    def[(size_t)idx * 2 + 1] = gy + fy * t;
}

// ---------------------------------------------------------------------------
// Patch extraction (grid_sample bilinear, zeros padding)
// ---------------------------------------------------------------------------
__global__ void patches_kernel(const float* __restrict__ x,
                               const float* __restrict__ def,
                               float* __restrict__ out)
{
    int bn = blockIdx.x;
    int b = bn >> 8;
    int n = bn & 255;
    int hy = n >> 4;
    int wx = n & 15;
    const float* dptr = def + (((size_t)(b * IMG_H + hy * STRIDE_) * IMG_W) + wx * STRIDE_) * 2;
    float cx = dptr[0];
    float cy = dptr[1];

    for (int p = threadIdx.x; p < PATCH * PATCH; p += blockDim.x) {
        int i = p >> 6;
        int j = p & 63;
        float pxv = -1.0f + 2.0f * (float)j / (float)(PATCH - 1);
        float pyv = -1.0f + 2.0f * (float)i / (float)(PATCH - 1);
        float gx = cx + pxv * ((float)PATCH / (float)IMG_W);
        float gy = cy + pyv * ((float)PATCH / (float)IMG_H);
        float ix = ((gx + 1.0f) * (float)IMG_W - 1.0f) * 0.5f;
        float iy = ((gy + 1.0f) * (float)IMG_H - 1.0f) * 0.5f;
        float x0f = floorf(ix), y0f = floorf(iy);
        float wx1 = ix - x0f, wy1 = iy - y0f;
        int x0 = (int)x0f, y0 = (int)y0f;
        int x1 = x0 + 1, y1 = y0 + 1;
        bool vx0 = (x0 >= 0) & (x0 <= IMG_W - 1);
        bool vx1 = (x1 >= 0) & (x1 <= IMG_W - 1);
        bool vy0 = (y0 >= 0) & (y0 <= IMG_H - 1);
        bool vy1 = (y1 >= 0) & (y1 <= IMG_H - 1);
        int x0c = min(max(x0, 0), IMG_W - 1);
        int x1c = min(max(x1, 0), IMG_W - 1);
        int y0c = min(max(y0, 0), IMG_H - 1);
        int y1c = min(max(y1, 0), IMG_H - 1);
        float w00 = (1.f - wx1) * (1.f - wy1) * (float)(vx0 && vy0);
        float w10 = wx1 * (1.f - wy1) * (float)(vx1 && vy0);
        float w01 = (1.f - wx1) * wy1 * (float)(vx0 && vy1);
        float w11 = wx1 * wy1 * (float)(vx1 && vy1);

#pragma unroll
        for (int c = 0; c < 3; c++) {
            const float* img = x + (size_t)(b * 3 + c) * IMG_H * IMG_W;
            float v = img[y0c * IMG_W + x0c] * w00
                    + img[y0c * IMG_W + x1c] * w10
                    + img[y1c * IMG_W + x0c] * w01
                    + img[y1c * IMG_W + x1c] * w11;
            out[((size_t)(bn)*3 + c) * (PATCH * PATCH) + p] = v;
        }
    }
}

// ---------------------------------------------------------------------------
// Launch
// ---------------------------------------------------------------------------
#define SMEM_C2_8 ((2 * (10 * 68 * 16) + 2 * (9 * 32 * 16)) * 2)   // 61,952 B
#define SMEM_C4_4 ((2 * (10 * 36 * 16) + 2 * (9 * 64 * 16)) * 2)   // 59,904 B
#define SMEM_C1_8 ((2 * (10 * 68 * 16) + 2 * (9 * 16 * 16)) * 2)   // 52,736 B

extern "C" void kernel_launch(void* const* d_in, const int* in_sizes, int n_in,
                              void* d_out, int out_size)
{
    const float* x  = (const float*)d_in[0];
    const float* w0 = (const float*)d_in[1];  const float* b0 = (const float*)d_in[2];
    const float* w1 = (const float*)d_in[3];  const float* b1 = (const float*)d_in[4];
    const float* w2 = (const float*)d_in[5];  const float* b2 = (const float*)d_in[6];
    const float* w3 = (const float*)d_in[7];  const float* b3 = (const float*)d_in[8];
    const float* w4 = (const float*)d_in[9];  const float* b4 = (const float*)d_in[10];
    const float* w5 = (const float*)d_in[11]; const float* b5 = (const float*)d_in[12];
    const float* w6 = (const float*)d_in[13]; const float* b6 = (const float*)d_in[14];
    const float* w7 = (const float*)d_in[15]; const float* b7 = (const float*)d_in[16];
    const float* temp = (const float*)d_in[17];

    float* out     = (float*)d_out;
    float* patches = out;
    float* flow    = out + PATCHES_ELEMS;
    float* def     = out + PATCHES_ELEMS + FLOW_ELEMS;

    float* A;  cudaGetSymbolAddress((void**)&A, g_bufA);
    float* Bb; cudaGetSymbolAddress((void**)&Bb, g_bufB);
    __nv_bfloat16* WH; cudaGetSymbolAddress((void**)&WH, g_wh);
    __nv_bfloat16* WL; cudaGetSymbolAddress((void**)&WL, g_wl);

    __nv_bfloat16* Ahi = (__nv_bfloat16*)A;
    __nv_bfloat16* Alo = Ahi + PLANE_ELEMS;
    __nv_bfloat16* Bhi = (__nv_bfloat16*)Bb;
    __nv_bfloat16* Blo = Bhi + PLANE_ELEMS;

    cudaFuncSetAttribute((const void*)conv_mma_kernel<2, 8, 1, 0>,
                         cudaFuncAttributeMaxDynamicSharedMemorySize, SMEM_C2_8);
    cudaFuncSetAttribute((const void*)conv_mma_kernel<4, 4, 1, 0>,
                         cudaFuncAttributeMaxDynamicSharedMemorySize, SMEM_C4_4);
    cudaFuncSetAttribute((const void*)conv_mma_kernel<1, 8, 2, 1>,
                         cudaFuncAttributeMaxDynamicSharedMemorySize, SMEM_C1_8);

    // ---- preconvert ALL weights in one launch ----
    wconv_all<<<(WSCRATCH + 255) / 256, 256>>>(w0, w1, w2, w3, w4, w5, w6, w7, WH, WL);

    // ---- x -> bf16 act layout (B) ----
    {
        int total = BATCH * IMG_H * IMG_W * 16;
        xcvt_kernel<<<(total + 255) / 256, 256>>>(x, Bhi, Blo);
    }

    // ---- flow net (ping-pong B <-> A); all GRPS=1 ----
    // conv0: 3->32 @512 relu  (B -> A)
    conv_mma_kernel<2, 8, 1, 0><<<dim3(8, 64, 4), 256, SMEM_C2_8>>>(
        Bhi, Blo, WH + 0, WL + 0, b0, Ahi, Alo, nullptr, 512, 512, 1, 32, 1);
    // conv1: 32->32 @512 relu (A -> B)
    conv_mma_kernel<2, 8, 1, 0><<<dim3(8, 64, 4), 256, SMEM_C2_8>>>(
        Ahi, Alo, WH + 4608, WL + 4608, b1, Bhi, Blo, nullptr, 512, 512, 2, 32, 1);
    // pool: 512->256          (B -> A)
    {
        int total = BATCH * 2 * 256 * 256 * 16;
        pool_bf16<<<(total + 255) / 256, 256>>>(Bhi, Blo, Ahi, Alo, total, 256, 256);
    }
    // conv2: 32->64 @256 relu (A -> B)  NCT=4, 32-wide, all couts in one pass
    conv_mma_kernel<4, 4, 1, 0><<<dim3(8, 32, 4), 256, SMEM_C4_4>>>(
        Ahi, Alo, WH + 13824, WL + 13824, b2, Bhi, Blo, nullptr, 256, 256, 2, 64, 1);
    // conv3: 64->64 @256 relu (B -> A)
    conv_mma_kernel<4, 4, 1, 0><<<dim3(8, 32, 4), 256, SMEM_C4_4>>>(
        Bhi, Blo, WH + 32256, WL + 32256, b3, Ahi, Alo, nullptr, 256, 256, 4, 64, 1);
    // pool: 256->128          (A -> B)
    {
        int total = BATCH * 4 * 128 * 128 * 16;
        pool_bf16<<<(total + 255) / 256, 256>>>(Ahi, Alo, Bhi, Blo, total, 128, 128);
    }
    // up: 128->256            (B -> A)
    {
        int total = BATCH * 4 * 256 * 256 * 16;
        up_bf16<<<(total + 255) / 256, 256>>>(Bhi, Blo, Ahi, Alo, total, 128, 128);
    }
    // conv4: 64->64 @256 relu (A -> B)
    conv_mma_kernel<4, 4, 1, 0><<<dim3(8, 32, 4), 256, SMEM_C4_4>>>(
        Ahi, Alo, WH + 69120, WL + 69120, b4, Bhi, Blo, nullptr, 256, 256, 4, 64, 1);
    // conv5: 64->32 @256 relu (B -> A)  NCT=2, 64-wide
    conv_mma_kernel<2, 8, 1, 0><<<dim3(4, 32, 4), 256, SMEM_C2_8>>>(
        Bhi, Blo, WH + 105984, WL + 105984, b5, Ahi, Alo, nullptr, 256, 256, 4, 32, 1);
    // up: 256->512            (A -> B)
    {
        int total = BATCH * 2 * 512 * 512 * 16;
        up_bf16<<<(total + 255) / 256, 256>>>(Ahi, Alo, Bhi, Blo, total, 256, 256);
    }
    // conv6: 32->32 @512 relu (B -> A)
    conv_mma_kernel<2, 8, 1, 0><<<dim3(8, 64, 4), 256, SMEM_C2_8>>>(
        Bhi, Blo, WH + 124416, WL + 124416, b6, Ahi, Alo, nullptr, 512, 512, 2, 32, 1);
    // conv7: 32->2 @512 tanh  (A -> flow, fp32)
    conv_mma_kernel<1, 8, 2, 1><<<dim3(8, 64, 4), 256, SMEM_C1_8>>>(
        Ahi, Alo, WH + 133632, WL + 133632, b7, nullptr, nullptr, flow, 512, 512, 2, 2, 1);

    // deformed grid
    {
        int total = BATCH * IMG_H * IMG_W;
        deform_kernel<<<(total + 255) / 256, 256>>>(flow, temp, def);
    }
    // patches
    patches_kernel<<<dim3(BATCH * NPATCH), 256>>>(x, def, patches);
}

// round 11
// speedup vs baseline: 1.1746x; 1.0499x over previous
#include <cuda_runtime.h>
#include <cuda_bf16.h>
#include <math.h>

// ---------------------------------------------------------------------------
// Problem constants
// ---------------------------------------------------------------------------
#define BATCH 4
#define IMG_H 512
#define IMG_W 512
#define PATCH 64
#define STRIDE_ 32
#define NPATCH 256
#define PATCHES_ELEMS (BATCH * NPATCH * 3 * PATCH * PATCH)   // 12,582,912
#define FLOW_ELEMS    (BATCH * 2 * IMG_H * IMG_W)            //  2,097,152

// Scratch (device globals). Each 33.5M floats = 67.1M bf16 = hi+lo planes.
__device__ __align__(256) float g_bufA[33554432];
__device__ __align__(256) float g_bufB[33554432];
#define PLANE_ELEMS 33554432

// Preconverted weights (bf16 hi/lo, pos16-permuted).
#define WSCRATCH 138240
__device__ __align__(256) __nv_bfloat16 g_wh[WSCRATCH];
__device__ __align__(256) __nv_bfloat16 g_wl[WSCRATCH];

// ---------------------------------------------------------------------------
// helpers
// ---------------------------------------------------------------------------
__device__ __forceinline__ void cp_async16(void* smem_dst, const void* gptr) {
    unsigned sa = (unsigned)__cvta_generic_to_shared(smem_dst);
    asm volatile("cp.async.cg.shared.global [%0], [%1], 16;" :: "r"(sa), "l"(gptr));
}
__device__ __forceinline__ void cp_commit() { asm volatile("cp.async.commit_group;"); }
__device__ __forceinline__ void cp_wait0()  { asm volatile("cp.async.wait_group 0;"); }

__device__ __forceinline__ void mma16816(float* c, const unsigned* a, unsigned b0, unsigned b1) {
    asm volatile(
        "mma.sync.aligned.m16n8k16.row.col.f32.bf16.bf16.f32 "
        "{%0,%1,%2,%3}, {%4,%5,%6,%7}, {%8,%9}, {%0,%1,%2,%3};"
        : "+f"(c[0]), "+f"(c[1]), "+f"(c[2]), "+f"(c[3])
        : "r"(a[0]), "r"(a[1]), "r"(a[2]), "r"(a[3]), "r"(b0), "r"(b1));
}

// pos16(2q)=4q, pos16(2q+1)=4q+1, pos16(2q+8)=4q+2, pos16(2q+9)=4q+3 (q=0..3)
__device__ __forceinline__ int pos16(int ci) {
    return (((ci >> 1) & 3) << 2) + (((ci >> 3) & 1) << 1) + (ci & 1);
}
__device__ __forceinline__ void bf16split(float v, __nv_bfloat16& h, __nv_bfloat16& l) {
    h = __float2bfloat16(v);
    l = __float2bfloat16(v - __bfloat162float(h));
}

// ---------------------------------------------------------------------------
// Fused weight preconversion for ALL 8 layers in one launch.
// ---------------------------------------------------------------------------
__constant__ int c_woffs[9]  = {0, 4608, 13824, 32256, 69120, 105984, 124416, 133632, 138240};
__constant__ int c_wCOUT[8]  = {32, 32, 64, 64, 64, 32, 32, 2};
__constant__ int c_wCIN[8]   = {3, 32, 32, 64, 64, 64, 32, 32};
__constant__ int c_wCOUTP[8] = {32, 32, 64, 64, 64, 32, 32, 16};

__global__ void wconv_all(const float* __restrict__ w0, const float* __restrict__ w1,
                          const float* __restrict__ w2, const float* __restrict__ w3,
                          const float* __restrict__ w4, const float* __restrict__ w5,
                          const float* __restrict__ w6, const float* __restrict__ w7,
                          __nv_bfloat16* __restrict__ dh, __nv_bfloat16* __restrict__ dl)
{
    int idx = blockIdx.x * blockDim.x + threadIdx.x;
    if (idx >= WSCRATCH) return;
    int l = 0;
    while (idx >= c_woffs[l + 1]) l++;
    int rel = idx - c_woffs[l];
    int COUT = c_wCOUT[l], CIN = c_wCIN[l], COUTP = c_wCOUTP[l];
    int ci = rel & 15;
    int t = rel >> 4;
    int co = t % COUTP;  t /= COUTP;
    int tap = t % 9;
    int cb = t / 9;
    const float* w;
    switch (l) {
        case 0: w = w0; break; case 1: w = w1; break;
        case 2: w = w2; break; case 3: w = w3; break;
        case 4: w = w4; break; case 5: w = w5; break;
        case 6: w = w6; break; default: w = w7; break;
    }
    int ci_g = cb * 16 + ci;
    float v = 0.f;
    if (co < COUT && ci_g < CIN)
        v = w[((size_t)co * CIN + ci_g) * 9 + tap];
    __nv_bfloat16 h, lo;
    bf16split(v, h, lo);
    int base = idx & ~15;
    dh[base + pos16(ci)] = h;
    dl[base + pos16(ci)] = lo;
}

// ---------------------------------------------------------------------------
// x (fp32 NCHW, C=3) -> act layout [b][cb=0][y][x][pos16(ci)], ci>=3 zero
// ---------------------------------------------------------------------------
__global__ void xcvt_kernel(const float* __restrict__ x,
                            __nv_bfloat16* __restrict__ ohi,
                            __nv_bfloat16* __restrict__ olo)
{
    int idx = blockIdx.x * blockDim.x + threadIdx.x;
    int total = BATCH * IMG_H * IMG_W * 16;
    if (idx >= total) return;
    int ci = idx & 15;
    int p = idx >> 4;
    int xx = p % IMG_W;
    int yy = (p / IMG_W) % IMG_H;
    int b  = p / (IMG_W * IMG_H);
    float v = 0.f;
    if (ci < 3)
        v = x[((size_t)(b * 3 + ci) * IMG_H + yy) * IMG_W + xx];
    __nv_bfloat16 h, l;
    bf16split(v, h, l);
    size_t o = ((size_t)p << 4) + pos16(ci);
    ohi[o] = h;
    olo[o] = l;
}

// ---------------------------------------------------------------------------
// Implicit-GEMM 3x3 conv via mma.sync bf16 (3-term hi/lo split).
// Tile: (NT*8) wide x 8 tall x (NCT*16) couts. 256 threads (8 warps).
// OUTMODE: 0 = bf16 act layout (+relu)
//          1 = fp32 NCHW (+tanh)
//          2 = bf16 act layout, fused bias+relu+MaxPool2x2 (H/2 x W/2 out)
// ---------------------------------------------------------------------------
template <int NCT, int NT, int ACT, int OUTMODE>
__global__ void __launch_bounds__(256, 2)
conv_mma_kernel(const __nv_bfloat16* __restrict__ ghi,
                const __nv_bfloat16* __restrict__ glo,
                const __nv_bfloat16* __restrict__ gwh,
                const __nv_bfloat16* __restrict__ gwl,
                const float* __restrict__ bias,
                __nv_bfloat16* __restrict__ ohi,
                __nv_bfloat16* __restrict__ olo,
                float* __restrict__ of32,
                int H, int W, int CBIN, int COUT, int GRPS)
{
    constexpr int COUTP = NCT * 16;
    constexpr int TILEW = NT * 8;
    constexpr int PITCH = TILEW + 4;
    constexpr int IN_PLANE = 10 * PITCH * 16;
    constexpr int WPL = 9 * COUTP * 16;
    extern __shared__ char smraw[];
    __nv_bfloat16* s_hi = (__nv_bfloat16*)smraw;
    __nv_bfloat16* s_lo = s_hi + IN_PLANE;
    __nv_bfloat16* s_wh = s_hi + 2 * IN_PLANE;
    __nv_bfloat16* s_wl = s_wh + WPL;

    const int bx = blockIdx.x * TILEW;
    const int by = blockIdx.y * 8;
    const int grp = blockIdx.z % GRPS;
    const int b   = blockIdx.z / GRPS;

    const int tid  = threadIdx.x;
    const int warp = tid >> 5;
    const int lane = tid & 31;
    const int gid  = lane >> 2;   // 0..7
    const int qid  = lane & 3;    // 0..3

    float acc[NCT][NT][4];
#pragma unroll
    for (int ct = 0; ct < NCT; ct++)
#pragma unroll
        for (int nt = 0; nt < NT; nt++) {
            acc[ct][nt][0] = 0.f; acc[ct][nt][1] = 0.f;
            acc[ct][nt][2] = 0.f; acc[ct][nt][3] = 0.f;
        }

    for (int cb = 0; cb < CBIN; cb++) {
        __syncthreads();
        // ---- stage weights (raw bf16 copy) ----
        {
            const __nv_bfloat16* pwh = gwh + ((size_t)grp * CBIN + cb) * WPL;
            const __nv_bfloat16* pwl = gwl + ((size_t)grp * CBIN + cb) * WPL;
            for (int idx = tid * 8; idx < WPL; idx += 2048) {
                cp_async16(s_wh + idx, pwh + idx);
                cp_async16(s_wl + idx, pwl + idx);
            }
        }
        // ---- stage input chunk: 10 x (TILEW+2) pixels, 32B/pixel/plane ----
        for (int p = tid; p < 10 * (TILEW + 2); p += 256) {
            int row = p / (TILEW + 2);
            int col = p - row * (TILEW + 2);
            int gy = by + row - 1;
            int gx = bx + col - 1;
            int soff = (row * PITCH + col) * 16;
            if (gy >= 0 && gy < H && gx >= 0 && gx < W) {
                size_t g = ((((size_t)b * CBIN + cb) * H + gy) * W + gx) << 4;
                cp_async16(s_hi + soff,     ghi + g);
                cp_async16(s_hi + soff + 8, ghi + g + 8);
                cp_async16(s_lo + soff,     glo + g);
                cp_async16(s_lo + soff + 8, glo + g + 8);
            } else {
                uint4 z = make_uint4(0u, 0u, 0u, 0u);
                *(uint4*)(s_hi + soff) = z; *(uint4*)(s_hi + soff + 8) = z;
                *(uint4*)(s_lo + soff) = z; *(uint4*)(s_lo + soff + 8) = z;
            }
        }
        cp_commit();
        cp_wait0();
        __syncthreads();

        // ---- compute: 9 taps ----
        int ky = 0, kx = 0;
#pragma unroll 1
        for (int tap = 0; tap < 9; tap++) {
            unsigned ah[NCT][4], al[NCT][4];
            const int wbase = tap * COUTP * 16 + 4 * qid;
#pragma unroll
            for (int ct = 0; ct < NCT; ct++) {
                int co_l = ct * 16 + gid;
                uint2 h0 = *(const uint2*)(s_wh + wbase + co_l * 16);
                uint2 h1 = *(const uint2*)(s_wh + wbase + (co_l + 8) * 16);
                ah[ct][0] = h0.x; ah[ct][2] = h0.y;
                ah[ct][1] = h1.x; ah[ct][3] = h1.y;
                uint2 l0 = *(const uint2*)(s_wl + wbase + co_l * 16);
                uint2 l1 = *(const uint2*)(s_wl + wbase + (co_l + 8) * 16);
                al[ct][0] = l0.x; al[ct][2] = l0.y;
                al[ct][1] = l1.x; al[ct][3] = l1.y;
            }
            const int rowb = warp + ky;
#pragma unroll
            for (int nt = 0; nt < NT; nt++) {
                int colb = nt * 8 + gid + kx;
                int ibase = (rowb * PITCH + colb) * 16 + 4 * qid;
                uint2 bh = *(const uint2*)(s_hi + ibase);
                uint2 bl = *(const uint2*)(s_lo + ibase);
#pragma unroll
                for (int ct = 0; ct < NCT; ct++) {
                    mma16816(acc[ct][nt], ah[ct], bh.x, bh.y);
                    mma16816(acc[ct][nt], ah[ct], bl.x, bl.y);
                    mma16816(acc[ct][nt], al[ct], bh.x, bh.y);
                }
            }
            if (++kx == 3) { kx = 0; ++ky; }
        }
    }

    // ---- epilogue ----
    const int gy = by + warp;
    if (OUTMODE == 1) {
#pragma unroll
        for (int ct = 0; ct < NCT; ct++) {
            int co0r = grp * COUTP + ct * 16 + gid;
            int co1r = co0r + 8;
            bool ok0 = co0r < COUT;
            bool ok1 = co1r < COUT;
            float bv0 = ok0 ? bias[co0r] : 0.f;
            float bv1 = ok1 ? bias[co1r] : 0.f;
#pragma unroll
            for (int nt = 0; nt < NT; nt++) {
                int gxv = bx + nt * 8 + 2 * qid;
                if (ok0) {
                    float v0 = tanhf(acc[ct][nt][0] + bv0);
                    float v1 = tanhf(acc[ct][nt][1] + bv0);
                    *(float2*)&of32[((size_t)(b * COUT + co0r) * H + gy) * W + gxv]
                        = make_float2(v0, v1);
                }
                if (ok1) {
                    float v0 = tanhf(acc[ct][nt][2] + bv1);
                    float v1 = tanhf(acc[ct][nt][3] + bv1);
                    *(float2*)&of32[((size_t)(b * COUT + co1r) * H + gy) * W + gxv]
                        = make_float2(v0, v1);
                }
            }
        }
    } else if (OUTMODE == 0) {
        const int nCBo = COUT >> 4;
        const int slot0 = pos16(gid);
        const int slot1 = slot0 + 2;
#pragma unroll
        for (int ct = 0; ct < NCT; ct++) {
            int co_g = grp * COUTP + ct * 16 + gid;
            int cbo = co_g >> 4;
            float bv0 = bias[co_g];
            float bv1 = bias[co_g + 8];
#pragma unroll
            for (int nt = 0; nt < NT; nt++) {
                int gxv = bx + nt * 8 + 2 * qid;
                size_t g = ((((size_t)b * nCBo + cbo) * H + gy) * W + gxv) << 4;
                float v0 = acc[ct][nt][0] + bv0;
                float v1 = acc[ct][nt][1] + bv0;
                float v2 = acc[ct][nt][2] + bv1;
                float v3 = acc[ct][nt][3] + bv1;
                if (ACT == 1) {
                    v0 = fmaxf(v0, 0.f); v1 = fmaxf(v1, 0.f);
                    v2 = fmaxf(v2, 0.f); v3 = fmaxf(v3, 0.f);
                }
                __nv_bfloat16 h, l;
                bf16split(v0, h, l); ohi[g + slot0]      = h; olo[g + slot0]      = l;
                bf16split(v1, h, l); ohi[g + 16 + slot0] = h; olo[g + 16 + slot0] = l;
                bf16split(v2, h, l); ohi[g + slot1]      = h; olo[g + slot1]      = l;
                bf16split(v3, h, l); ohi[g + 16 + slot1] = h; olo[g + 16 + slot1] = l;
            }
        }
    } else {
        // OUTMODE 2: fused bias + relu + MaxPool 2x2.
        // (v0,v1) / (v2,v3) are aligned horizontal pool pairs (gxv even).
        constexpr int PW = NT * 4;          // pooled tile width
        constexpr int PC = COUTP + 1;       // padded smem stride
        float* s_pool = (float*)smraw;      // reuse input/weight smem
        __syncthreads();                    // all compute done before reuse
#pragma unroll
        for (int ct = 0; ct < NCT; ct++) {
            float bv0 = bias[ct * 16 + gid];
            float bv1 = bias[ct * 16 + 8 + gid];
#pragma unroll
            for (int nt = 0; nt < NT; nt++) {
                float v0 = fmaxf(acc[ct][nt][0] + bv0, 0.f);
                float v1 = fmaxf(acc[ct][nt][1] + bv0, 0.f);
                float v2 = fmaxf(acc[ct][nt][2] + bv1, 0.f);
                float v3 = fmaxf(acc[ct][nt][3] + bv1, 0.f);
                int px = nt * 4 + qid;
                s_pool[(warp * PW + px) * PC + ct * 16 + gid]     = fmaxf(v0, v1);
                s_pool[(warp * PW + px) * PC + ct * 16 + 8 + gid] = fmaxf(v2, v3);
            }
        }
        __syncthreads();
        const int H2 = H >> 1, W2 = W >> 1;
        const int nCBo = COUT >> 4;
        constexpr int TOTP = 4 * PW * COUTP;
        for (int v = tid; v < TOTP; v += 256) {
            int co = v & (COUTP - 1);
            int rest = v >> (NCT == 4 ? 6 : 5);
            int px = rest & (PW - 1);
            int prow = rest / PW;
            float a = s_pool[((2 * prow) * PW + px) * PC + co];
            float bq = s_pool[((2 * prow + 1) * PW + px) * PC + co];
            float m = fmaxf(a, bq);
            int gy2 = (by >> 1) + prow;
            int gx2 = (bx >> 1) + px;
            int cbo = co >> 4;
            int slot = pos16(co & 15);
            size_t g = ((((size_t)b * nCBo + cbo) * H2 + gy2) * W2 + gx2) * 16 + slot;
            __nv_bfloat16 h, l;
            bf16split(m, h, l);
            ohi[g] = h;
            olo[g] = l;
        }
    }
}

// ---------------------------------------------------------------------------
// Bilinear upsample x2 on bf16 hi/lo act layout (slot-preserving)
// ---------------------------------------------------------------------------
__global__ void up_bf16(const __nv_bfloat16* __restrict__ ihi,
                        const __nv_bfloat16* __restrict__ ilo,
                        __nv_bfloat16* __restrict__ ohi,
                        __nv_bfloat16* __restrict__ olo,
                        int total, int Hin, int Win)
{
    int idx = blockIdx.x * blockDim.x + threadIdx.x;
    if (idx >= total) return;
    int slot = idx & 15;
    int p = idx >> 4;
    int Hout = 2 * Hin, Wout = 2 * Win;
    int ox = p % Wout;
    int t = p / Wout;
    int oy = t % Hout;
    int c = t / Hout;

    float fy = (oy + 0.5f) * 0.5f - 0.5f;
    float fx = (ox + 0.5f) * 0.5f - 0.5f;
    int y0 = (int)floorf(fy);
    int x0 = (int)floorf(fx);
    float wy = fy - (float)y0;
    float wx = fx - (float)x0;
    int y0c = max(y0, 0), y1c = min(y0 + 1, Hin - 1);
    int x0c = max(x0, 0), x1c = min(x0 + 1, Win - 1);

    size_t cb = (size_t)c * Hin;
    size_t o00 = ((cb + y0c) * Win + x0c) * 16 + slot;
    size_t o01 = ((cb + y0c) * Win + x1c) * 16 + slot;
    size_t o10 = ((cb + y1c) * Win + x0c) * 16 + slot;
    size_t o11 = ((cb + y1c) * Win + x1c) * 16 + slot;
    float v00 = __bfloat162float(ihi[o00]) + __bfloat162float(ilo[o00]);
    float v01 = __bfloat162float(ihi[o01]) + __bfloat162float(ilo[o01]);
    float v10 = __bfloat162float(ihi[o10]) + __bfloat162float(ilo[o10]);
    float v11 = __bfloat162float(ihi[o11]) + __bfloat162float(ilo[o11]);
    float v = (1.f - wy) * ((1.f - wx) * v00 + wx * v01)
            +        wy  * ((1.f - wx) * v10 + wx * v11);
    __nv_bfloat16 h, l;
    bf16split(v, h, l);
    ohi[idx] = h;
    olo[idx] = l;
}

// ---------------------------------------------------------------------------
// deformed = base_grid + flow^T * temp
// ---------------------------------------------------------------------------
__global__ void deform_kernel(const float* __restrict__ flow,
                              const float* __restrict__ temp,
                              float* __restrict__ def)
{
    int idx = blockIdx.x * blockDim.x + threadIdx.x;
    int total = BATCH * IMG_H * IMG_W;
    if (idx >= total) return;
    int w = idx % IMG_W;
    int h = (idx / IMG_W) % IMG_H;
    int b = idx / (IMG_W * IMG_H);
    float gx = -1.0f + 2.0f * (float)w / (float)(IMG_W - 1);
    float gy = -1.0f + 2.0f * (float)h / (float)(IMG_H - 1);
    float t = temp[0];
    float fx = flow[((size_t)(b * 2 + 0) * IMG_H + h) * IMG_W + w];
    float fy = flow[((size_t)(b * 2 + 1) * IMG_H + h) * IMG_W + w];
    def[(size_t)idx * 2 + 0] = gx + fx * t;
    def[(size_t)idx * 2 + 1] = gy + fy * t;
}

// ---------------------------------------------------------------------------
// Patch extraction (grid_sample bilinear, zeros padding)
// ---------------------------------------------------------------------------
__global__ void patches_kernel(const float* __restrict__ x,
                               const float* __restrict__ def,
                               float* __restrict__ out)
{
    int bn = blockIdx.x;
    int b = bn >> 8;
    int n = bn & 255;
    int hy = n >> 4;
    int wx = n & 15;
    const float* dptr = def + (((size_t)(b * IMG_H + hy * STRIDE_) * IMG_W) + wx * STRIDE_) * 2;
    float cx = dptr[0];
    float cy = dptr[1];

    for (int p = threadIdx.x; p < PATCH * PATCH; p += blockDim.x) {
        int i = p >> 6;
        int j = p & 63;
        float pxv = -1.0f + 2.0f * (float)j / (float)(PATCH - 1);
        float pyv = -1.0f + 2.0f * (float)i / (float)(PATCH - 1);
        float gx = cx + pxv * ((float)PATCH / (float)IMG_W);
        float gy = cy + pyv * ((float)PATCH / (float)IMG_H);
        float ix = ((gx + 1.0f) * (float)IMG_W - 1.0f) * 0.5f;
        float iy = ((gy + 1.0f) * (float)IMG_H - 1.0f) * 0.5f;
        float x0f = floorf(ix), y0f = floorf(iy);
        float wx1 = ix - x0f, wy1 = iy - y0f;
        int x0 = (int)x0f, y0 = (int)y0f;
        int x1 = x0 + 1, y1 = y0 + 1;
        bool vx0 = (x0 >= 0) & (x0 <= IMG_W - 1);
        bool vx1 = (x1 >= 0) & (x1 <= IMG_W - 1);
        bool vy0 = (y0 >= 0) & (y0 <= IMG_H - 1);
        bool vy1 = (y1 >= 0) & (y1 <= IMG_H - 1);
        int x0c = min(max(x0, 0), IMG_W - 1);
        int x1c = min(max(x1, 0), IMG_W - 1);
        int y0c = min(max(y0, 0), IMG_H - 1);
        int y1c = min(max(y1, 0), IMG_H - 1);
        float w00 = (1.f - wx1) * (1.f - wy1) * (float)(vx0 && vy0);
        float w10 = wx1 * (1.f - wy1) * (float)(vx1 && vy0);
        float w01 = (1.f - wx1) * wy1 * (float)(vx0 && vy1);
        float w11 = wx1 * wy1 * (float)(vx1 && vy1);

#pragma unroll
        for (int c = 0; c < 3; c++) {
            const float* img = x + (size_t)(b * 3 + c) * IMG_H * IMG_W;
            float v = img[y0c * IMG_W + x0c] * w00
                    + img[y0c * IMG_W + x1c] * w10
                    + img[y1c * IMG_W + x0c] * w01
                    + img[y1c * IMG_W + x1c] * w11;
            out[((size_t)(bn)*3 + c) * (PATCH * PATCH) + p] = v;
        }
    }
}

// ---------------------------------------------------------------------------
// Launch
// ---------------------------------------------------------------------------
#define SMEM_C2_8 ((2 * (10 * 68 * 16) + 2 * (9 * 32 * 16)) * 2)   // 61,952 B
#define SMEM_C4_4 ((2 * (10 * 36 * 16) + 2 * (9 * 64 * 16)) * 2)   // 59,904 B
#define SMEM_C1_8 ((2 * (10 * 68 * 16) + 2 * (9 * 16 * 16)) * 2)   // 52,736 B

extern "C" void kernel_launch(void* const* d_in, const int* in_sizes, int n_in,
                              void* d_out, int out_size)
{
    const float* x  = (const float*)d_in[0];
    const float* w0 = (const float*)d_in[1];  const float* b0 = (const float*)d_in[2];
    const float* w1 = (const float*)d_in[3];  const float* b1 = (const float*)d_in[4];
    const float* w2 = (const float*)d_in[5];  const float* b2 = (const float*)d_in[6];
    const float* w3 = (const float*)d_in[7];  const float* b3 = (const float*)d_in[8];
    const float* w4 = (const float*)d_in[9];  const float* b4 = (const float*)d_in[10];
    const float* w5 = (const float*)d_in[11]; const float* b5 = (const float*)d_in[12];
    const float* w6 = (const float*)d_in[13]; const float* b6 = (const float*)d_in[14];
    const float* w7 = (const float*)d_in[15]; const float* b7 = (const float*)d_in[16];
    const float* temp = (const float*)d_in[17];

    float* out     = (float*)d_out;
    float* patches = out;
    float* flow    = out + PATCHES_ELEMS;
    float* def     = out + PATCHES_ELEMS + FLOW_ELEMS;

    float* A;  cudaGetSymbolAddress((void**)&A, g_bufA);
    float* Bb; cudaGetSymbolAddress((void**)&Bb, g_bufB);
    __nv_bfloat16* WH; cudaGetSymbolAddress((void**)&WH, g_wh);
    __nv_bfloat16* WL; cudaGetSymbolAddress((void**)&WL, g_wl);

    __nv_bfloat16* Ahi = (__nv_bfloat16*)A;
    __nv_bfloat16* Alo = Ahi + PLANE_ELEMS;
    __nv_bfloat16* Bhi = (__nv_bfloat16*)Bb;
    __nv_bfloat16* Blo = Bhi + PLANE_ELEMS;

    cudaFuncSetAttribute((const void*)conv_mma_kernel<2, 8, 1, 0>,
                         cudaFuncAttributeMaxDynamicSharedMemorySize, SMEM_C2_8);
    cudaFuncSetAttribute((const void*)conv_mma_kernel<2, 8, 1, 2>,
                         cudaFuncAttributeMaxDynamicSharedMemorySize, SMEM_C2_8);
    cudaFuncSetAttribute((const void*)conv_mma_kernel<4, 4, 1, 0>,
                         cudaFuncAttributeMaxDynamicSharedMemorySize, SMEM_C4_4);
    cudaFuncSetAttribute((const void*)conv_mma_kernel<4, 4, 1, 2>,
                         cudaFuncAttributeMaxDynamicSharedMemorySize, SMEM_C4_4);
    cudaFuncSetAttribute((const void*)conv_mma_kernel<1, 8, 2, 1>,
                         cudaFuncAttributeMaxDynamicSharedMemorySize, SMEM_C1_8);

    // ---- preconvert ALL weights in one launch ----
    wconv_all<<<(WSCRATCH + 255) / 256, 256>>>(w0, w1, w2, w3, w4, w5, w6, w7, WH, WL);

    // ---- x -> bf16 act layout (B) ----
    {
        int total = BATCH * IMG_H * IMG_W * 16;
        xcvt_kernel<<<(total + 255) / 256, 256>>>(x, Bhi, Blo);
    }

    // ---- flow net ----
    // conv0: 3->32 @512 relu          (B -> A)
    conv_mma_kernel<2, 8, 1, 0><<<dim3(8, 64, 4), 256, SMEM_C2_8>>>(
        Bhi, Blo, WH + 0, WL + 0, b0, Ahi, Alo, nullptr, 512, 512, 1, 32, 1);
    // conv1+pool: 32->32 @512 relu, pooled to 256²  (A -> B)
    conv_mma_kernel<2, 8, 1, 2><<<dim3(8, 64, 4), 256, SMEM_C2_8>>>(
        Ahi, Alo, WH + 4608, WL + 4608, b1, Bhi, Blo, nullptr, 512, 512, 2, 32, 1);
    // conv2: 32->64 @256 relu         (B -> A)
    conv_mma_kernel<4, 4, 1, 0><<<dim3(8, 32, 4), 256, SMEM_C4_4>>>(
        Bhi, Blo, WH + 13824, WL + 13824, b2, Ahi, Alo, nullptr, 256, 256, 2, 64, 1);
    // conv3+pool: 64->64 @256 relu, pooled to 128²  (A -> B)
    conv_mma_kernel<4, 4, 1, 2><<<dim3(8, 32, 4), 256, SMEM_C4_4>>>(
        Ahi, Alo, WH + 32256, WL + 32256, b3, Bhi, Blo, nullptr, 256, 256, 4, 64, 1);
    // up: 128->256                    (B -> A)
    {
        int total = BATCH * 4 * 256 * 256 * 16;
        up_bf16<<<(total + 255) / 256, 256>>>(Bhi, Blo, Ahi, Alo, total, 128, 128);
    }
    // conv4: 64->64 @256 relu         (A -> B)
    conv_mma_kernel<4, 4, 1, 0><<<dim3(8, 32, 4), 256, SMEM_C4_4>>>(
        Ahi, Alo, WH + 69120, WL + 69120, b4, Bhi, Blo, nullptr, 256, 256, 4, 64, 1);
    // conv5: 64->32 @256 relu         (B -> A)
    conv_mma_kernel<2, 8, 1, 0><<<dim3(4, 32, 4), 256, SMEM_C2_8>>>(
        Bhi, Blo, WH + 105984, WL + 105984, b5, Ahi, Alo, nullptr, 256, 256, 4, 32, 1);
    // up: 256->512                    (A -> B)
    {
        int total = BATCH * 2 * 512 * 512 * 16;
        up_bf16<<<(total + 255) / 256, 256>>>(Ahi, Alo, Bhi, Blo, total, 256, 256);
    }
    // conv6: 32->32 @512 relu         (B -> A)
    conv_mma_kernel<2, 8, 1, 0><<<dim3(8, 64, 4), 256, SMEM_C2_8>>>(
        Bhi, Blo, WH + 124416, WL + 124416, b6, Ahi, Alo, nullptr, 512, 512, 2, 32, 1);
    // conv7: 32->2 @512 tanh          (A -> flow, fp32)
    conv_mma_kernel<1, 8, 2, 1><<<dim3(8, 64, 4), 256, SMEM_C1_8>>>(
        Ahi, Alo, WH + 133632, WL + 133632, b7, nullptr, nullptr, flow, 512, 512, 2, 2, 1);

    // deformed grid
    {
        int total = BATCH * IMG_H * IMG_W;
        deform_kernel<<<(total + 255) / 256, 256>>>(flow, temp, def);
    }
    // patches
    patches_kernel<<<dim3(BATCH * NPATCH), 256>>>(x, def, patches);
}

// round 12
// speedup vs baseline: 1.2154x; 1.0348x over previous
#include <cuda_runtime.h>
#include <cuda_bf16.h>
#include <math.h>

// ---------------------------------------------------------------------------
// Problem constants
// ---------------------------------------------------------------------------
#define BATCH 4
#define IMG_H 512
#define IMG_W 512
#define PATCH 64
#define STRIDE_ 32
#define NPATCH 256
#define PATCHES_ELEMS (BATCH * NPATCH * 3 * PATCH * PATCH)   // 12,582,912
#define FLOW_ELEMS    (BATCH * 2 * IMG_H * IMG_W)            //  2,097,152

// Scratch (device globals). Activation = interleaved hi/lo, 32 bf16 per pixel.
// Max tensor: 4b * 2cb * 512 * 512 * 32 bf16 = 67.1M bf16 = 134MB = one buffer.
__device__ __align__(256) float g_bufA[33554432];
__device__ __align__(256) float g_bufB[33554432];

// Packed weights: per (layer, cb, tap, ct): [32 lanes x 16B hi][32 lanes x 16B lo]
#define WSCRATCH2 276480
__device__ __align__(256) __nv_bfloat16 g_wpk[WSCRATCH2];

// ---------------------------------------------------------------------------
// helpers
// ---------------------------------------------------------------------------
__device__ __forceinline__ void cp_async16(void* smem_dst, const void* gptr) {
    unsigned sa = (unsigned)__cvta_generic_to_shared(smem_dst);
    asm volatile("cp.async.cg.shared.global [%0], [%1], 16;" :: "r"(sa), "l"(gptr));
}
__device__ __forceinline__ void cp_commit() { asm volatile("cp.async.commit_group;"); }
__device__ __forceinline__ void cp_wait0()  { asm volatile("cp.async.wait_group 0;"); }

__device__ __forceinline__ void mma16816(float* c, const unsigned* a, unsigned b0, unsigned b1) {
    asm volatile(
        "mma.sync.aligned.m16n8k16.row.col.f32.bf16.bf16.f32 "
        "{%0,%1,%2,%3}, {%4,%5,%6,%7}, {%8,%9}, {%0,%1,%2,%3};"
        : "+f"(c[0]), "+f"(c[1]), "+f"(c[2]), "+f"(c[3])
        : "r"(a[0]), "r"(a[1]), "r"(a[2]), "r"(a[3]), "r"(b0), "r"(b1));
}

// slot permutation within 16 channels: pos16(2q)=4q, pos16(2q+1)=4q+1,
// pos16(2q+8)=4q+2, pos16(2q+9)=4q+3  (q=0..3)
__device__ __forceinline__ int pos16(int ci) {
    return (((ci >> 1) & 3) << 2) + (((ci >> 3) & 1) << 1) + (ci & 1);
}
// v2 act layout: pixel stride 32 bf16; group g=slot>>2: bytes [16g..16g+8)=hi
// slots 4g..4g+3, [16g+8..16g+16)=lo.  hi offset = 8*(s>>2)+(s&3), lo = +4.
__device__ __forceinline__ int hoff16(int s) { return 8 * (s >> 2) + (s & 3); }

__device__ __forceinline__ void bf16split(float v, __nv_bfloat16& h, __nv_bfloat16& l) {
    h = __float2bfloat16(v);
    l = __float2bfloat16(v - __bfloat162float(h));
}

// ---------------------------------------------------------------------------
// Fused weight preconversion: fp32 -> packed per-lane mma A-fragments.
// Per (cb,tap,ct) unit of 512 bf16: [hi: lane*8 + e][lo: 256 + lane*8 + e]
// e=0..7: j=e>>1, kk=e&1;  co = ct*16 + gid + (j&1)*8;  k = 2*q + kk + (j&2)*4
// ---------------------------------------------------------------------------
__constant__ int c_woffs2[9] = {0, 9216, 27648, 64512, 138240, 211968, 248832, 267264, 276480};
__constant__ int c_wCOUT[8]  = {32, 32, 64, 64, 64, 32, 32, 2};
__constant__ int c_wCIN[8]   = {3, 32, 32, 64, 64, 64, 32, 32};
__constant__ int c_wNCT[8]   = {2, 2, 4, 4, 4, 2, 2, 1};

__global__ void wconv_all(const float* __restrict__ w0, const float* __restrict__ w1,
                          const float* __restrict__ w2, const float* __restrict__ w3,
                          const float* __restrict__ w4, const float* __restrict__ w5,
                          const float* __restrict__ w6, const float* __restrict__ w7,
                          __nv_bfloat16* __restrict__ dst)
{
    int idx = blockIdx.x * blockDim.x + threadIdx.x;
    if (idx >= WSCRATCH2) return;
    int l = 0;
    while (idx >= c_woffs2[l + 1]) l++;
    int rel = idx - c_woffs2[l];
    int COUT = c_wCOUT[l], CIN = c_wCIN[l], NCT = c_wNCT[l];
    int e    = rel & 255;
    int plane = (rel >> 8) & 1;
    int unit = rel >> 9;
    int ct  = unit % NCT;  unit /= NCT;
    int tap = unit % 9;
    int cb  = unit / 9;
    int lane = e >> 3;
    int e8 = e & 7;
    int j = e8 >> 1, kk = e8 & 1;
    int gid = lane >> 2, q = lane & 3;
    int co = ct * 16 + gid + (j & 1) * 8;
    int k  = 2 * q + kk + ((j & 2) ? 8 : 0);
    int ci_g = cb * 16 + k;
    const float* w;
    switch (l) {
        case 0: w = w0; break; case 1: w = w1; break;
        case 2: w = w2; break; case 3: w = w3; break;
        case 4: w = w4; break; case 5: w = w5; break;
        case 6: w = w6; break; default: w = w7; break;
    }
    float v = 0.f;
    if (co < COUT && ci_g < CIN)
        v = w[((size_t)co * CIN + ci_g) * 9 + tap];
    __nv_bfloat16 h = __float2bfloat16(v);
    dst[idx] = plane ? __float2bfloat16(v - __bfloat162float(h)) : h;
}

// ---------------------------------------------------------------------------
// x (fp32 NCHW, C=3) -> interleaved act layout, ci>=3 zero
// ---------------------------------------------------------------------------
__global__ void xcvt_kernel(const float* __restrict__ x, __nv_bfloat16* __restrict__ oact)
{
    int idx = blockIdx.x * blockDim.x + threadIdx.x;
    int total = BATCH * IMG_H * IMG_W * 16;
    if (idx >= total) return;
    int ci = idx & 15;
    int p = idx >> 4;
    int xx = p % IMG_W;
    int yy = (p / IMG_W) % IMG_H;
    int b  = p / (IMG_W * IMG_H);
    float v = 0.f;
    if (ci < 3)
        v = x[((size_t)(b * 3 + ci) * IMG_H + yy) * IMG_W + xx];
    __nv_bfloat16 h, l;
    bf16split(v, h, l);
    size_t o = (size_t)p * 32 + hoff16(pos16(ci));
    oact[o] = h;
    oact[o + 4] = l;
}

// ---------------------------------------------------------------------------
// Implicit-GEMM 3x3 conv via mma.sync bf16 (3-term hi/lo split), layout v2.
// Tile: (NT*8) wide x 8 tall x (NCT*16) couts. 256 threads (8 warps).
// OUTMODE: 0 = act layout (+relu); 1 = fp32 NCHW (+tanh);
//          2 = act layout, fused bias+relu+MaxPool2x2
// ---------------------------------------------------------------------------
template <int NCT, int NT, int OUTMODE>
__global__ void __launch_bounds__(256, 2)
conv_mma_kernel(const __nv_bfloat16* __restrict__ gact,
                const __nv_bfloat16* __restrict__ gw,
                const float* __restrict__ bias,
                __nv_bfloat16* __restrict__ oact,
                float* __restrict__ of32,
                int H, int W, int CBIN, int COUT)
{
    constexpr int COUTP = NCT * 16;
    constexpr int TILEW = NT * 8;
    constexpr int PITCH = TILEW + 4;
    constexpr int INP = 10 * PITCH * 32;      // bf16
    constexpr int WPL = 9 * NCT * 512;        // bf16 per cb chunk
    extern __shared__ char smraw[];
    __nv_bfloat16* s_act = (__nv_bfloat16*)smraw;
    __nv_bfloat16* s_w   = s_act + INP;

    const int bx = blockIdx.x * TILEW;
    const int by = blockIdx.y * 8;
    const int b  = blockIdx.z;

    const int tid  = threadIdx.x;
    const int warp = tid >> 5;
    const int lane = tid & 31;
    const int gid  = lane >> 2;
    const int qid  = lane & 3;

    float acc[NCT][NT][4];
#pragma unroll
    for (int ct = 0; ct < NCT; ct++)
#pragma unroll
        for (int nt = 0; nt < NT; nt++) {
            acc[ct][nt][0] = 0.f; acc[ct][nt][1] = 0.f;
            acc[ct][nt][2] = 0.f; acc[ct][nt][3] = 0.f;
        }

    for (int cb = 0; cb < CBIN; cb++) {
        __syncthreads();
        // ---- stage weights (raw bf16 copy, already fragment-packed) ----
        {
            const __nv_bfloat16* pw = gw + (size_t)cb * WPL;
            for (int idx = tid * 8; idx < WPL; idx += 2048)
                cp_async16(s_w + idx, pw + idx);
        }
        // ---- stage input: 10 x (TILEW+2) pixels, 64B/pixel raw copy ----
        for (int p = tid; p < 10 * (TILEW + 2); p += 256) {
            int row = p / (TILEW + 2);
            int col = p - row * (TILEW + 2);
            int gy = by + row - 1;
            int gx = bx + col - 1;
            int soff = (row * PITCH + col) * 32;
            if (gy >= 0 && gy < H && gx >= 0 && gx < W) {
                size_t g = ((((size_t)b * CBIN + cb) * H + gy) * W + gx) * 32;
                cp_async16(s_act + soff,      gact + g);
                cp_async16(s_act + soff + 8,  gact + g + 8);
                cp_async16(s_act + soff + 16, gact + g + 16);
                cp_async16(s_act + soff + 24, gact + g + 24);
            } else {
                uint4 z = make_uint4(0u, 0u, 0u, 0u);
                *(uint4*)(s_act + soff)      = z;
                *(uint4*)(s_act + soff + 8)  = z;
                *(uint4*)(s_act + soff + 16) = z;
                *(uint4*)(s_act + soff + 24) = z;
            }
        }
        cp_commit();
        cp_wait0();
        __syncthreads();

        // ---- compute: 9 taps ----
        int ky = 0, kx = 0;
#pragma unroll 1
        for (int tap = 0; tap < 9; tap++) {
            unsigned ah[NCT][4], al[NCT][4];
            const int wb = tap * NCT * 512 + lane * 8;
#pragma unroll
            for (int ct = 0; ct < NCT; ct++) {
                uint4 hv = *(const uint4*)(s_w + wb + ct * 512);
                uint4 lv = *(const uint4*)(s_w + wb + ct * 512 + 256);
                ah[ct][0] = hv.x; ah[ct][1] = hv.y; ah[ct][2] = hv.z; ah[ct][3] = hv.w;
                al[ct][0] = lv.x; al[ct][1] = lv.y; al[ct][2] = lv.z; al[ct][3] = lv.w;
            }
            const int rowb = warp + ky;
#pragma unroll
            for (int nt = 0; nt < NT; nt++) {
                int colb = nt * 8 + gid + kx;
                uint4 bv = *(const uint4*)(s_act + (rowb * PITCH + colb) * 32 + 8 * qid);
#pragma unroll
                for (int ct = 0; ct < NCT; ct++) {
                    mma16816(acc[ct][nt], ah[ct], bv.x, bv.y);
                    mma16816(acc[ct][nt], ah[ct], bv.z, bv.w);
                    mma16816(acc[ct][nt], al[ct], bv.x, bv.y);
                }
            }
            if (++kx == 3) { kx = 0; ++ky; }
        }
    }

    // ---- epilogue ----
    const int gy = by + warp;
    if (OUTMODE == 1) {
#pragma unroll
        for (int ct = 0; ct < NCT; ct++) {
            int co0r = ct * 16 + gid;
            int co1r = co0r + 8;
            bool ok0 = co0r < COUT;
            bool ok1 = co1r < COUT;
            float bv0 = ok0 ? bias[co0r] : 0.f;
            float bv1 = ok1 ? bias[co1r] : 0.f;
#pragma unroll
            for (int nt = 0; nt < NT; nt++) {
                int gxv = bx + nt * 8 + 2 * qid;
                if (ok0) {
                    float v0 = tanhf(acc[ct][nt][0] + bv0);
                    float v1 = tanhf(acc[ct][nt][1] + bv0);
                    *(float2*)&of32[((size_t)(b * COUT + co0r) * H + gy) * W + gxv]
                        = make_float2(v0, v1);
                }
                if (ok1) {
                    float v0 = tanhf(acc[ct][nt][2] + bv1);
                    float v1 = tanhf(acc[ct][nt][3] + bv1);
                    *(float2*)&of32[((size_t)(b * COUT + co1r) * H + gy) * W + gxv]
                        = make_float2(v0, v1);
                }
            }
        }
    } else if (OUTMODE == 0) {
        const int nCBo = COUT >> 4;
        const int s0 = 4 * (gid >> 1) + (gid & 1);
        const int hf0 = hoff16(s0);
        const int hf1 = hf0 + 2;       // slot s0+2, same group
#pragma unroll
        for (int ct = 0; ct < NCT; ct++) {
            int co_g = ct * 16 + gid;
            int cbo = co_g >> 4;
            float bv0 = bias[co_g];
            float bv1 = bias[co_g + 8];
#pragma unroll
            for (int nt = 0; nt < NT; nt++) {
                int gxv = bx + nt * 8 + 2 * qid;
                size_t g = ((((size_t)b * nCBo + cbo) * H + gy) * W + gxv) * 32;
                float v0 = fmaxf(acc[ct][nt][0] + bv0, 0.f);
                float v1 = fmaxf(acc[ct][nt][1] + bv0, 0.f);
                float v2 = fmaxf(acc[ct][nt][2] + bv1, 0.f);
                float v3 = fmaxf(acc[ct][nt][3] + bv1, 0.f);
                __nv_bfloat16 h, l;
                bf16split(v0, h, l); oact[g + hf0]          = h; oact[g + hf0 + 4]      = l;
                bf16split(v1, h, l); oact[g + 32 + hf0]     = h; oact[g + 32 + hf0 + 4] = l;
                bf16split(v2, h, l); oact[g + hf1]          = h; oact[g + hf1 + 4]      = l;
                bf16split(v3, h, l); oact[g + 32 + hf1]     = h; oact[g + 32 + hf1 + 4] = l;
            }
        }
    } else {
        // OUTMODE 2: fused bias + relu + MaxPool 2x2
        constexpr int PW = NT * 4;
        constexpr int PC = COUTP + 1;
        float* s_pool = (float*)smraw;
        __syncthreads();
#pragma unroll
        for (int ct = 0; ct < NCT; ct++) {
            float bv0 = bias[ct * 16 + gid];
            float bv1 = bias[ct * 16 + 8 + gid];
#pragma unroll
            for (int nt = 0; nt < NT; nt++) {
                float v0 = fmaxf(acc[ct][nt][0] + bv0, 0.f);
                float v1 = fmaxf(acc[ct][nt][1] + bv0, 0.f);
                float v2 = fmaxf(acc[ct][nt][2] + bv1, 0.f);
                float v3 = fmaxf(acc[ct][nt][3] + bv1, 0.f);
                int px = nt * 4 + qid;
                s_pool[(warp * PW + px) * PC + ct * 16 + gid]     = fmaxf(v0, v1);
                s_pool[(warp * PW + px) * PC + ct * 16 + 8 + gid] = fmaxf(v2, v3);
            }
        }
        __syncthreads();
        const int H2 = H >> 1, W2 = W >> 1;
        const int nCBo = COUT >> 4;
        constexpr int TOTP = 4 * PW * COUTP;
        for (int v = tid; v < TOTP; v += 256) {
            int co = v & (COUTP - 1);
            int rest = v >> (NCT == 4 ? 6 : 5);
            int px = rest & (PW - 1);
            int prow = rest / PW;
            float a = s_pool[((2 * prow) * PW + px) * PC + co];
            float bq = s_pool[((2 * prow + 1) * PW + px) * PC + co];
            float m = fmaxf(a, bq);
            int gy2 = (by >> 1) + prow;
            int gx2 = (bx >> 1) + px;
            int cbo = co >> 4;
            int hf = hoff16(pos16(co & 15));
            size_t g = ((((size_t)b * nCBo + cbo) * H2 + gy2) * W2 + gx2) * 32;
            __nv_bfloat16 h, l;
            bf16split(m, h, l);
            oact[g + hf] = h;
            oact[g + hf + 4] = l;
        }
    }
}

// ---------------------------------------------------------------------------
// Bilinear upsample x2 on interleaved act layout (slot-preserving)
// ---------------------------------------------------------------------------
__global__ void up_bf16(const __nv_bfloat16* __restrict__ iact,
                        __nv_bfloat16* __restrict__ oact,
                        int total, int Hin, int Win)
{
    int idx = blockIdx.x * blockDim.x + threadIdx.x;
    if (idx >= total) return;
    int slot = idx & 15;
    int p = idx >> 4;
    int Hout = 2 * Hin, Wout = 2 * Win;
    int ox = p % Wout;
    int t = p / Wout;
    int oy = t % Hout;
    int c = t / Hout;
    int hf = hoff16(slot);

    float fy = (oy + 0.5f) * 0.5f - 0.5f;
    float fx = (ox + 0.5f) * 0.5f - 0.5f;
    int y0 = (int)floorf(fy);
    int x0 = (int)floorf(fx);
    float wy = fy - (float)y0;
    float wx = fx - (float)x0;
    int y0c = max(y0, 0), y1c = min(y0 + 1, Hin - 1);
    int x0c = max(x0, 0), x1c = min(x0 + 1, Win - 1);

    size_t cb = (size_t)c * Hin;
    size_t o00 = ((cb + y0c) * Win + x0c) * 32 + hf;
    size_t o01 = ((cb + y0c) * Win + x1c) * 32 + hf;
    size_t o10 = ((cb + y1c) * Win + x0c) * 32 + hf;
    size_t o11 = ((cb + y1c) * Win + x1c) * 32 + hf;
    float v00 = __bfloat162float(iact[o00]) + __bfloat162float(iact[o00 + 4]);
    float v01 = __bfloat162float(iact[o01]) + __bfloat162float(iact[o01 + 4]);
    float v10 = __bfloat162float(iact[o10]) + __bfloat162float(iact[o10 + 4]);
    float v11 = __bfloat162float(iact[o11]) + __bfloat162float(iact[o11 + 4]);
    float v = (1.f - wy) * ((1.f - wx) * v00 + wx * v01)
            +        wy  * ((1.f - wx) * v10 + wx * v11);
    __nv_bfloat16 h, l;
    bf16split(v, h, l);
    size_t o = (size_t)p * 32 + hf;
    oact[o] = h;
    oact[o + 4] = l;
}

// ---------------------------------------------------------------------------
// deformed = base_grid + flow^T * temp
// ---------------------------------------------------------------------------
__global__ void deform_kernel(const float* __restrict__ flow,
                              const float* __restrict__ temp,
                              float* __restrict__ def)
{
    int idx = blockIdx.x * blockDim.x + threadIdx.x;
    int total = BATCH * IMG_H * IMG_W;
    if (idx >= total) return;
    int w = idx % IMG_W;
    int h = (idx / IMG_W) % IMG_H;
    int b = idx / (IMG_W * IMG_H);
    float gx = -1.0f + 2.0f * (float)w / (float)(IMG_W - 1);
    float gy = -1.0f + 2.0f * (float)h / (float)(IMG_H - 1);
    float t = temp[0];
    float fx = flow[((size_t)(b * 2 + 0) * IMG_H + h) * IMG_W + w];
    float fy = flow[((size_t)(b * 2 + 1) * IMG_H + h) * IMG_W + w];
    def[(size_t)idx * 2 + 0] = gx + fx * t;
    def[(size_t)idx * 2 + 1] = gy + fy * t;
}

// ---------------------------------------------------------------------------
// Patch extraction (grid_sample bilinear, zeros padding)
// ---------------------------------------------------------------------------
__global__ void patches_kernel(const float* __restrict__ x,
                               const float* __restrict__ def,
                               float* __restrict__ out)
{
    int bn = blockIdx.x;
    int b = bn >> 8;
    int n = bn & 255;
    int hy = n >> 4;
    int wx = n & 15;
    const float* dptr = def + (((size_t)(b * IMG_H + hy * STRIDE_) * IMG_W) + wx * STRIDE_) * 2;
    float cx = dptr[0];
    float cy = dptr[1];

    for (int p = threadIdx.x; p < PATCH * PATCH; p += blockDim.x) {
        int i = p >> 6;
        int j = p & 63;
        float pxv = -1.0f + 2.0f * (float)j / (float)(PATCH - 1);
        float pyv = -1.0f + 2.0f * (float)i / (float)(PATCH - 1);
        float gx = cx + pxv * ((float)PATCH / (float)IMG_W);
        float gy = cy + pyv * ((float)PATCH / (float)IMG_H);
        float ix = ((gx + 1.0f) * (float)IMG_W - 1.0f) * 0.5f;
        float iy = ((gy + 1.0f) * (float)IMG_H - 1.0f) * 0.5f;
        float x0f = floorf(ix), y0f = floorf(iy);
        float wx1 = ix - x0f, wy1 = iy - y0f;
        int x0 = (int)x0f, y0 = (int)y0f;
        int x1 = x0 + 1, y1 = y0 + 1;
        bool vx0 = (x0 >= 0) & (x0 <= IMG_W - 1);
        bool vx1 = (x1 >= 0) & (x1 <= IMG_W - 1);
        bool vy0 = (y0 >= 0) & (y0 <= IMG_H - 1);
        bool vy1 = (y1 >= 0) & (y1 <= IMG_H - 1);
        int x0c = min(max(x0, 0), IMG_W - 1);
        int x1c = min(max(x1, 0), IMG_W - 1);
        int y0c = min(max(y0, 0), IMG_H - 1);
        int y1c = min(max(y1, 0), IMG_H - 1);
        float w00 = (1.f - wx1) * (1.f - wy1) * (float)(vx0 && vy0);
        float w10 = wx1 * (1.f - wy1) * (float)(vx1 && vy0);
        float w01 = (1.f - wx1) * wy1 * (float)(vx0 && vy1);
        float w11 = wx1 * wy1 * (float)(vx1 && vy1);

#pragma unroll
        for (int c = 0; c < 3; c++) {
            const float* img = x + (size_t)(b * 3 + c) * IMG_H * IMG_W;
            float v = img[y0c * IMG_W + x0c] * w00
                    + img[y0c * IMG_W + x1c] * w10
                    + img[y1c * IMG_W + x0c] * w01
                    + img[y1c * IMG_W + x1c] * w11;
            out[((size_t)(bn)*3 + c) * (PATCH * PATCH) + p] = v;
        }
    }
}

// ---------------------------------------------------------------------------
// Launch
// ---------------------------------------------------------------------------
#define SMEM_C2_8 ((10 * 68 * 32 + 9 * 2 * 512) * 2)   // 61,952 B
#define SMEM_C4_4 ((10 * 36 * 32 + 9 * 4 * 512) * 2)   // 59,904 B
#define SMEM_C1_8 ((10 * 68 * 32 + 9 * 1 * 512) * 2)   // 52,736 B

extern "C" void kernel_launch(void* const* d_in, const int* in_sizes, int n_in,
                              void* d_out, int out_size)
{
    const float* x  = (const float*)d_in[0];
    const float* w0 = (const float*)d_in[1];  const float* b0 = (const float*)d_in[2];
    const float* w1 = (const float*)d_in[3];  const float* b1 = (const float*)d_in[4];
    const float* w2 = (const float*)d_in[5];  const float* b2 = (const float*)d_in[6];
    const float* w3 = (const float*)d_in[7];  const float* b3 = (const float*)d_in[8];
    const float* w4 = (const float*)d_in[9];  const float* b4 = (const float*)d_in[10];
    const float* w5 = (const float*)d_in[11]; const float* b5 = (const float*)d_in[12];
    const float* w6 = (const float*)d_in[13]; const float* b6 = (const float*)d_in[14];
    const float* w7 = (const float*)d_in[15]; const float* b7 = (const float*)d_in[16];
    const float* temp = (const float*)d_in[17];

    float* out     = (float*)d_out;
    float* patches = out;
    float* flow    = out + PATCHES_ELEMS;
    float* def     = out + PATCHES_ELEMS + FLOW_ELEMS;

    float* A;  cudaGetSymbolAddress((void**)&A, g_bufA);
    float* Bb; cudaGetSymbolAddress((void**)&Bb, g_bufB);
    __nv_bfloat16* WP; cudaGetSymbolAddress((void**)&WP, g_wpk);

    __nv_bfloat16* Apk = (__nv_bfloat16*)A;
    __nv_bfloat16* Bpk = (__nv_bfloat16*)Bb;

    cudaFuncSetAttribute((const void*)conv_mma_kernel<2, 8, 0>,
                         cudaFuncAttributeMaxDynamicSharedMemorySize, SMEM_C2_8);
    cudaFuncSetAttribute((const void*)conv_mma_kernel<2, 8, 2>,
                         cudaFuncAttributeMaxDynamicSharedMemorySize, SMEM_C2_8);
    cudaFuncSetAttribute((const void*)conv_mma_kernel<4, 4, 0>,
                         cudaFuncAttributeMaxDynamicSharedMemorySize, SMEM_C4_4);
    cudaFuncSetAttribute((const void*)conv_mma_kernel<4, 4, 2>,
                         cudaFuncAttributeMaxDynamicSharedMemorySize, SMEM_C4_4);
    cudaFuncSetAttribute((const void*)conv_mma_kernel<1, 8, 1>,
                         cudaFuncAttributeMaxDynamicSharedMemorySize, SMEM_C1_8);

    // ---- preconvert ALL weights in one launch ----
    wconv_all<<<(WSCRATCH2 + 255) / 256, 256>>>(w0, w1, w2, w3, w4, w5, w6, w7, WP);

    // ---- x -> interleaved act layout (B) ----
    {
        int total = BATCH * IMG_H * IMG_W * 16;
        xcvt_kernel<<<(total + 255) / 256, 256>>>(x, Bpk);
    }

    // ---- flow net ----
    // conv0: 3->32 @512 relu          (B -> A)
    conv_mma_kernel<2, 8, 0><<<dim3(8, 64, 4), 256, SMEM_C2_8>>>(
        Bpk, WP + 0, b0, Apk, nullptr, 512, 512, 1, 32);
    // conv1+pool: 32->32 @512 relu -> 256²  (A -> B)
    conv_mma_kernel<2, 8, 2><<<dim3(8, 64, 4), 256, SMEM_C2_8>>>(
        Apk, WP + 9216, b1, Bpk, nullptr, 512, 512, 2, 32);
    // conv2: 32->64 @256 relu         (B -> A)
    conv_mma_kernel<4, 4, 0><<<dim3(8, 32, 4), 256, SMEM_C4_4>>>(
        Bpk, WP + 27648, b2, Apk, nullptr, 256, 256, 2, 64);
    // conv3+pool: 64->64 @256 relu -> 128²  (A -> B)
    conv_mma_kernel<4, 4, 2><<<dim3(8, 32, 4), 256, SMEM_C4_4>>>(
        Apk, WP + 64512, b3, Bpk, nullptr, 256, 256, 4, 64);
    // up: 128->256                    (B -> A)
    {
        int total = BATCH * 4 * 256 * 256 * 16;
        up_bf16<<<(total + 255) / 256, 256>>>(Bpk, Apk, total, 128, 128);
    }
    // conv4: 64->64 @256 relu         (A -> B)
    conv_mma_kernel<4, 4, 0><<<dim3(8, 32, 4), 256, SMEM_C4_4>>>(
        Apk, WP + 138240, b4, Bpk, nullptr, 256, 256, 4, 64);
    // conv5: 64->32 @256 relu         (B -> A)
    conv_mma_kernel<2, 8, 0><<<dim3(4, 32, 4), 256, SMEM_C2_8>>>(
        Bpk, WP + 211968, b5, Apk, nullptr, 256, 256, 4, 32);
    // up: 256->512                    (A -> B)
    {
        int total = BATCH * 2 * 512 * 512 * 16;
        up_bf16<<<(total + 255) / 256, 256>>>(Apk, Bpk, total, 256, 256);
    }
    // conv6: 32->32 @512 relu         (B -> A)
    conv_mma_kernel<2, 8, 0><<<dim3(8, 64, 4), 256, SMEM_C2_8>>>(
        Bpk, WP + 248832, b6, Apk, nullptr, 512, 512, 2, 32);
    // conv7: 32->2 @512 tanh          (A -> flow, fp32)
    conv_mma_kernel<1, 8, 1><<<dim3(8, 64, 4), 256, SMEM_C1_8>>>(
        Apk, WP + 267264, b7, nullptr, flow, 512, 512, 2, 2);

    // deformed grid
    {
        int total = BATCH * IMG_H * IMG_W;
        deform_kernel<<<(total + 255) / 256, 256>>>(flow, temp, def);
    }
    // patches
    patches_kernel<<<dim3(BATCH * NPATCH), 256>>>(x, def, patches);
}

// round 13
// speedup vs baseline: 1.3449x; 1.1066x over previous
#include <cuda_runtime.h>
#include <cuda_bf16.h>
#include <math.h>

// ---------------------------------------------------------------------------
// Problem constants
// ---------------------------------------------------------------------------
#define BATCH 4
#define IMG_H 512
#define IMG_W 512
#define PATCH 64
#define STRIDE_ 32
#define NPATCH 256
#define PATCHES_ELEMS (BATCH * NPATCH * 3 * PATCH * PATCH)   // 12,582,912
#define FLOW_ELEMS    (BATCH * 2 * IMG_H * IMG_W)            //  2,097,152

// Scratch (device globals). Activation = interleaved hi/lo, 32 bf16 per pixel.
__device__ __align__(256) float g_bufA[33554432];
__device__ __align__(256) float g_bufB[33554432];

// Packed weights: per (layer, cb, tap, ct): [32 lanes x 16B hi][32 lanes x 16B lo]
#define WSCRATCH2 276480
__device__ __align__(256) __nv_bfloat16 g_wpk[WSCRATCH2];

// ---------------------------------------------------------------------------
// helpers
// ---------------------------------------------------------------------------
__device__ __forceinline__ unsigned su32(const void* p) {
    return (unsigned)__cvta_generic_to_shared(p);
}
__device__ __forceinline__ void cp_async16(void* smem_dst, const void* gptr) {
    asm volatile("cp.async.cg.shared.global [%0], [%1], 16;"
                 :: "r"(su32(smem_dst)), "l"(gptr));
}
__device__ __forceinline__ void cp_commit() { asm volatile("cp.async.commit_group;"); }
__device__ __forceinline__ void cp_wait0()  { asm volatile("cp.async.wait_group 0;"); }

__device__ __forceinline__ void cp_bulk(unsigned sdst, const void* g, unsigned bytes,
                                        unsigned mbar) {
    asm volatile(
        "cp.async.bulk.shared::cta.global.mbarrier::complete_tx::bytes [%0], [%1], %2, [%3];"
        :: "r"(sdst), "l"(g), "r"(bytes), "r"(mbar) : "memory");
}
__device__ __forceinline__ void mbar_init(unsigned addr, unsigned cnt) {
    asm volatile("mbarrier.init.shared.b64 [%0], %1;" :: "r"(addr), "r"(cnt) : "memory");
}
__device__ __forceinline__ void mbar_expect_tx(unsigned addr, unsigned bytes) {
    asm volatile("mbarrier.arrive.expect_tx.shared.b64 _, [%0], %1;"
                 :: "r"(addr), "r"(bytes) : "memory");
}
__device__ __forceinline__ void mbar_wait(unsigned addr, unsigned parity) {
    asm volatile(
        "{\n\t.reg .pred P;\n\t"
        "W_%=:\n\t"
        "mbarrier.try_wait.parity.acquire.cta.shared::cta.b64 P, [%0], %1, 0x989680;\n\t"
        "@P bra.uni D_%=;\n\t"
        "bra.uni W_%=;\n\t"
        "D_%=:\n\t}"
        :: "r"(addr), "r"(parity) : "memory");
}

__device__ __forceinline__ void mma16816(float* c, const unsigned* a, unsigned b0, unsigned b1) {
    asm volatile(
        "mma.sync.aligned.m16n8k16.row.col.f32.bf16.bf16.f32 "
        "{%0,%1,%2,%3}, {%4,%5,%6,%7}, {%8,%9}, {%0,%1,%2,%3};"
        : "+f"(c[0]), "+f"(c[1]), "+f"(c[2]), "+f"(c[3])
        : "r"(a[0]), "r"(a[1]), "r"(a[2]), "r"(a[3]), "r"(b0), "r"(b1));
}

// slot permutation within 16 channels
__device__ __forceinline__ int pos16(int ci) {
    return (((ci >> 1) & 3) << 2) + (((ci >> 3) & 1) << 1) + (ci & 1);
}
// interleaved layout: hi offset = 8*(s>>2)+(s&3), lo = +4
__device__ __forceinline__ int hoff16(int s) { return 8 * (s >> 2) + (s & 3); }

__device__ __forceinline__ void bf16split(float v, __nv_bfloat16& h, __nv_bfloat16& l) {
    h = __float2bfloat16(v);
    l = __float2bfloat16(v - __bfloat162float(h));
}

// ---------------------------------------------------------------------------
// Fused weight preconversion: fp32 -> packed per-lane mma A-fragments.
// ---------------------------------------------------------------------------
__constant__ int c_woffs2[9] = {0, 9216, 27648, 64512, 138240, 211968, 248832, 267264, 276480};
__constant__ int c_wCOUT[8]  = {32, 32, 64, 64, 64, 32, 32, 2};
__constant__ int c_wCIN[8]   = {3, 32, 32, 64, 64, 64, 32, 32};
__constant__ int c_wNCT[8]   = {2, 2, 4, 4, 4, 2, 2, 1};

__global__ void wconv_all(const float* __restrict__ w0, const float* __restrict__ w1,
                          const float* __restrict__ w2, const float* __restrict__ w3,
                          const float* __restrict__ w4, const float* __restrict__ w5,
                          const float* __restrict__ w6, const float* __restrict__ w7,
                          __nv_bfloat16* __restrict__ dst)
{
    int idx = blockIdx.x * blockDim.x + threadIdx.x;
    if (idx >= WSCRATCH2) return;
    int l = 0;
    while (idx >= c_woffs2[l + 1]) l++;
    int rel = idx - c_woffs2[l];
    int COUT = c_wCOUT[l], CIN = c_wCIN[l], NCT = c_wNCT[l];
    int e    = rel & 255;
    int plane = (rel >> 8) & 1;
    int unit = rel >> 9;
    int ct  = unit % NCT;  unit /= NCT;
    int tap = unit % 9;
    int cb  = unit / 9;
    int lane = e >> 3;
    int e8 = e & 7;
    int j = e8 >> 1, kk = e8 & 1;
    int gid = lane >> 2, q = lane & 3;
    int co = ct * 16 + gid + (j & 1) * 8;
    int k  = 2 * q + kk + ((j & 2) ? 8 : 0);
    int ci_g = cb * 16 + k;
    const float* w;
    switch (l) {
        case 0: w = w0; break; case 1: w = w1; break;
        case 2: w = w2; break; case 3: w = w3; break;
        case 4: w = w4; break; case 5: w = w5; break;
        case 6: w = w6; break; default: w = w7; break;
    }
    float v = 0.f;
    if (co < COUT && ci_g < CIN)
        v = w[((size_t)co * CIN + ci_g) * 9 + tap];
    __nv_bfloat16 h = __float2bfloat16(v);
    dst[idx] = plane ? __float2bfloat16(v - __bfloat162float(h)) : h;
}

// ---------------------------------------------------------------------------
// Implicit-GEMM 3x3 conv via mma.sync bf16 (3-term hi/lo split), layout v2.
// Tile: (NT*8) wide x 8 tall x (NCT*16) couts. 256 threads (8 warps).
// Staging: cp.async.bulk rows + weight chunk into mbarrier (INX=0), or
// direct fp32->bf16 conversion from x (INX=1, conv0 only).
// OUTMODE: 0 = act layout (+relu); 1 = fp32 NCHW (+tanh);
//          2 = act layout, fused bias+relu+MaxPool2x2
// ---------------------------------------------------------------------------
template <int NCT, int NT, int OUTMODE, int INX>
__global__ void __launch_bounds__(256, 2)
conv_mma_kernel(const __nv_bfloat16* __restrict__ gact,
                const float* __restrict__ xin,
                const __nv_bfloat16* __restrict__ gw,
                const float* __restrict__ bias,
                __nv_bfloat16* __restrict__ oact,
                float* __restrict__ of32,
                int H, int W, int CBIN, int COUT)
{
    constexpr int COUTP = NCT * 16;
    constexpr int TILEW = NT * 8;
    constexpr int PITCH = TILEW + 4;
    constexpr int INP = 10 * PITCH * 32;      // bf16
    constexpr int WPL = 9 * NCT * 512;        // bf16 per cb chunk
    extern __shared__ char smraw[];
    __nv_bfloat16* s_act = (__nv_bfloat16*)smraw;
    __nv_bfloat16* s_w   = s_act + INP;
    const unsigned mbar  = su32(smraw) + (INP + WPL) * 2;

    const int bx = blockIdx.x * TILEW;
    const int by = blockIdx.y * 8;
    const int b  = blockIdx.z;

    const int tid  = threadIdx.x;
    const int warp = tid >> 5;
    const int lane = tid & 31;
    const int gid  = lane >> 2;
    const int qid  = lane & 3;

    float acc[NCT][NT][4];
#pragma unroll
    for (int ct = 0; ct < NCT; ct++)
#pragma unroll
        for (int nt = 0; nt < NT; nt++) {
            acc[ct][nt][0] = 0.f; acc[ct][nt][1] = 0.f;
            acc[ct][nt][2] = 0.f; acc[ct][nt][3] = 0.f;
        }

    // halo geometry (static per CTA)
    const bool topOOB = (by == 0);
    const bool botOOB = (by + 8 >= H);
    const bool leftOOB = (bx == 0);
    const bool rightOOB = (bx + TILEW >= W);
    const int r0 = topOOB ? 1 : 0;
    const int r1 = botOOB ? 9 : 10;
    const int c0 = leftOOB ? 1 : 0;
    const int c1 = rightOOB ? (TILEW + 1) : (TILEW + 2);

    int phase = 0;
    if (!INX) {
        if (tid == 0) mbar_init(mbar, 1);
        // zero-fill OOB halo ONCE (bulk copies never touch these cells)
        for (int p = tid; p < 10 * (TILEW + 2); p += 256) {
            int row = p / (TILEW + 2);
            int col = p - row * (TILEW + 2);
            if (row < r0 || row >= r1 || col < c0 || col >= c1) {
                uint4 z = make_uint4(0u, 0u, 0u, 0u);
                uint4* d = (uint4*)(s_act + (row * PITCH + col) * 32);
                d[0] = z; d[1] = z; d[2] = z; d[3] = z;
            }
        }
    }
    const unsigned rowBytes = (unsigned)(c1 - c0) * 64u;
    const unsigned txBytes  = (unsigned)(r1 - r0) * rowBytes + (unsigned)WPL * 2u;

    for (int cb = 0; cb < CBIN; cb++) {
        __syncthreads();    // prev compute done (cb=0: zero-fill/init visible)
        if (INX) {
            // conv0: stage weights via cp.async, input converted from fp32 x
            for (int idx = tid * 8; idx < WPL; idx += 2048)
                cp_async16(s_w + idx, gw + idx);
            for (int p = tid; p < 10 * (TILEW + 2); p += 256) {
                int row = p / (TILEW + 2);
                int col = p - row * (TILEW + 2);
                int gy = by + row - 1;
                int gx = bx + col - 1;
                __nv_bfloat16 arr[32];
#pragma unroll
                for (int i = 0; i < 32; i++) arr[i] = __float2bfloat16(0.f);
                if (gy >= 0 && gy < H && gx >= 0 && gx < W) {
#pragma unroll
                    for (int ci = 0; ci < 3; ci++) {
                        float v = xin[((size_t)(b * 3 + ci) * H + gy) * W + gx];
                        __nv_bfloat16 h, l;
                        bf16split(v, h, l);
                        int hf = hoff16(pos16(ci));
                        arr[hf] = h;
                        arr[hf + 4] = l;
                    }
                }
                uint4* src = (uint4*)arr;
                uint4* dst = (uint4*)(s_act + (row * PITCH + col) * 32);
                dst[0] = src[0]; dst[1] = src[1]; dst[2] = src[2]; dst[3] = src[3];
            }
            cp_commit();
            cp_wait0();
            __syncthreads();
        } else {
            if (tid == 0) {
                mbar_expect_tx(mbar, txBytes);
                for (int r = r0; r < r1; r++) {
                    int gy = by + r - 1;
                    const __nv_bfloat16* src = gact +
                        ((((size_t)b * CBIN + cb) * H + gy) * W + (bx + c0 - 1)) * 32;
                    cp_bulk(su32(s_act + (r * PITCH + c0) * 32), src, rowBytes, mbar);
                }
                cp_bulk(su32(s_w), gw + (size_t)cb * WPL, (unsigned)WPL * 2u, mbar);
            }
            mbar_wait(mbar, (unsigned)phase);
            phase ^= 1;
        }

        // ---- compute: 9 taps ----
        int ky = 0, kx = 0;
#pragma unroll 1
        for (int tap = 0; tap < 9; tap++) {
            unsigned ah[NCT][4], al[NCT][4];
            const int wb = tap * NCT * 512 + lane * 8;
#pragma unroll
            for (int ct = 0; ct < NCT; ct++) {
                uint4 hv = *(const uint4*)(s_w + wb + ct * 512);
                uint4 lv = *(const uint4*)(s_w + wb + ct * 512 + 256);
                ah[ct][0] = hv.x; ah[ct][1] = hv.y; ah[ct][2] = hv.z; ah[ct][3] = hv.w;
                al[ct][0] = lv.x; al[ct][1] = lv.y; al[ct][2] = lv.z; al[ct][3] = lv.w;
            }
            const int rowb = warp + ky;
#pragma unroll
            for (int nt = 0; nt < NT; nt++) {
                int colb = nt * 8 + gid + kx;
                uint4 bv = *(const uint4*)(s_act + (rowb * PITCH + colb) * 32 + 8 * qid);
#pragma unroll
                for (int ct = 0; ct < NCT; ct++) {
                    mma16816(acc[ct][nt], ah[ct], bv.x, bv.y);
                    mma16816(acc[ct][nt], ah[ct], bv.z, bv.w);
                    mma16816(acc[ct][nt], al[ct], bv.x, bv.y);
                }
            }
            if (++kx == 3) { kx = 0; ++ky; }
        }
    }

    // ---- epilogue ----
    const int gy = by + warp;
    if (OUTMODE == 1) {
#pragma unroll
        for (int ct = 0; ct < NCT; ct++) {
            int co0r = ct * 16 + gid;
            int co1r = co0r + 8;
            bool ok0 = co0r < COUT;
            bool ok1 = co1r < COUT;
            float bv0 = ok0 ? bias[co0r] : 0.f;
            float bv1 = ok1 ? bias[co1r] : 0.f;
#pragma unroll
            for (int nt = 0; nt < NT; nt++) {
                int gxv = bx + nt * 8 + 2 * qid;
                if (ok0) {
                    float v0 = tanhf(acc[ct][nt][0] + bv0);
                    float v1 = tanhf(acc[ct][nt][1] + bv0);
                    *(float2*)&of32[((size_t)(b * COUT + co0r) * H + gy) * W + gxv]
                        = make_float2(v0, v1);
                }
                if (ok1) {
                    float v0 = tanhf(acc[ct][nt][2] + bv1);
                    float v1 = tanhf(acc[ct][nt][3] + bv1);
                    *(float2*)&of32[((size_t)(b * COUT + co1r) * H + gy) * W + gxv]
                        = make_float2(v0, v1);
                }
            }
        }
    } else if (OUTMODE == 0) {
        const int nCBo = COUT >> 4;
        const int s0 = 4 * (gid >> 1) + (gid & 1);
        const int hf0 = hoff16(s0);
        const int hf1 = hf0 + 2;
#pragma unroll
        for (int ct = 0; ct < NCT; ct++) {
            int co_g = ct * 16 + gid;
            int cbo = co_g >> 4;
            float bv0 = bias[co_g];
            float bv1 = bias[co_g + 8];
#pragma unroll
            for (int nt = 0; nt < NT; nt++) {
                int gxv = bx + nt * 8 + 2 * qid;
                size_t g = ((((size_t)b * nCBo + cbo) * H + gy) * W + gxv) * 32;
                float v0 = fmaxf(acc[ct][nt][0] + bv0, 0.f);
                float v1 = fmaxf(acc[ct][nt][1] + bv0, 0.f);
                float v2 = fmaxf(acc[ct][nt][2] + bv1, 0.f);
                float v3 = fmaxf(acc[ct][nt][3] + bv1, 0.f);
                __nv_bfloat16 h, l;
                bf16split(v0, h, l); oact[g + hf0]          = h; oact[g + hf0 + 4]      = l;
                bf16split(v1, h, l); oact[g + 32 + hf0]     = h; oact[g + 32 + hf0 + 4] = l;
                bf16split(v2, h, l); oact[g + hf1]          = h; oact[g + hf1 + 4]      = l;
                bf16split(v3, h, l); oact[g + 32 + hf1]     = h; oact[g + 32 + hf1 + 4] = l;
            }
        }
    } else {
        // OUTMODE 2: fused bias + relu + MaxPool 2x2
        constexpr int PW = NT * 4;
        constexpr int PC = COUTP + 1;
        float* s_pool = (float*)smraw;
        __syncthreads();
#pragma unroll
        for (int ct = 0; ct < NCT; ct++) {
            float bv0 = bias[ct * 16 + gid];
            float bv1 = bias[ct * 16 + 8 + gid];
#pragma unroll
            for (int nt = 0; nt < NT; nt++) {
                float v0 = fmaxf(acc[ct][nt][0] + bv0, 0.f);
                float v1 = fmaxf(acc[ct][nt][1] + bv0, 0.f);
                float v2 = fmaxf(acc[ct][nt][2] + bv1, 0.f);
                float v3 = fmaxf(acc[ct][nt][3] + bv1, 0.f);
                int px = nt * 4 + qid;
                s_pool[(warp * PW + px) * PC + ct * 16 + gid]     = fmaxf(v0, v1);
                s_pool[(warp * PW + px) * PC + ct * 16 + 8 + gid] = fmaxf(v2, v3);
            }
        }
        __syncthreads();
        const int H2 = H >> 1, W2 = W >> 1;
        const int nCBo = COUT >> 4;
        constexpr int TOTP = 4 * PW * COUTP;
        for (int v = tid; v < TOTP; v += 256) {
            int co = v & (COUTP - 1);
            int rest = v >> (NCT == 4 ? 6 : 5);
            int px = rest & (PW - 1);
            int prow = rest / PW;
            float a = s_pool[((2 * prow) * PW + px) * PC + co];
            float bq = s_pool[((2 * prow + 1) * PW + px) * PC + co];
            float m = fmaxf(a, bq);
            int gy2 = (by >> 1) + prow;
            int gx2 = (bx >> 1) + px;
            int cbo = co >> 4;
            int hf = hoff16(pos16(co & 15));
            size_t g = ((((size_t)b * nCBo + cbo) * H2 + gy2) * W2 + gx2) * 32;
            __nv_bfloat16 h, l;
            bf16split(m, h, l);
            oact[g + hf] = h;
            oact[g + hf + 4] = l;
        }
    }
}

// ---------------------------------------------------------------------------
// Bilinear upsample x2 on interleaved act layout (slot-preserving)
// ---------------------------------------------------------------------------
__global__ void up_bf16(const __nv_bfloat16* __restrict__ iact,
                        __nv_bfloat16* __restrict__ oact,
                        int total, int Hin, int Win)
{
    int idx = blockIdx.x * blockDim.x + threadIdx.x;
    if (idx >= total) return;
    int slot = idx & 15;
    int p = idx >> 4;
    int Hout = 2 * Hin, Wout = 2 * Win;
    int ox = p % Wout;
    int t = p / Wout;
    int oy = t % Hout;
    int c = t / Hout;
    int hf = hoff16(slot);

    float fy = (oy + 0.5f) * 0.5f - 0.5f;
    float fx = (ox + 0.5f) * 0.5f - 0.5f;
    int y0 = (int)floorf(fy);
    int x0 = (int)floorf(fx);
    float wy = fy - (float)y0;
    float wx = fx - (float)x0;
    int y0c = max(y0, 0), y1c = min(y0 + 1, Hin - 1);
    int x0c = max(x0, 0), x1c = min(x0 + 1, Win - 1);

    size_t cb = (size_t)c * Hin;
    size_t o00 = ((cb + y0c) * Win + x0c) * 32 + hf;
    size_t o01 = ((cb + y0c) * Win + x1c) * 32 + hf;
    size_t o10 = ((cb + y1c) * Win + x0c) * 32 + hf;
    size_t o11 = ((cb + y1c) * Win + x1c) * 32 + hf;
    float v00 = __bfloat162float(iact[o00]) + __bfloat162float(iact[o00 + 4]);
    float v01 = __bfloat162float(iact[o01]) + __bfloat162float(iact[o01 + 4]);
    float v10 = __bfloat162float(iact[o10]) + __bfloat162float(iact[o10 + 4]);
    float v11 = __bfloat162float(iact[o11]) + __bfloat162float(iact[o11 + 4]);
    float v = (1.f - wy) * ((1.f - wx) * v00 + wx * v01)
            +        wy  * ((1.f - wx) * v10 + wx * v11);
    __nv_bfloat16 h, l;
    bf16split(v, h, l);
    size_t o = (size_t)p * 32 + hf;
    oact[o] = h;
    oact[o + 4] = l;
}

// ---------------------------------------------------------------------------
// deformed = base_grid + flow^T * temp
// ---------------------------------------------------------------------------
__global__ void deform_kernel(const float* __restrict__ flow,
                              const float* __restrict__ temp,
                              float* __restrict__ def)
{
    int idx = blockIdx.x * blockDim.x + threadIdx.x;
    int total = BATCH * IMG_H * IMG_W;
    if (idx >= total) return;
    int w = idx % IMG_W;
    int h = (idx / IMG_W) % IMG_H;
    int b = idx / (IMG_W * IMG_H);
    float gx = -1.0f + 2.0f * (float)w / (float)(IMG_W - 1);
    float gy = -1.0f + 2.0f * (float)h / (float)(IMG_H - 1);
    float t = temp[0];
    float fx = flow[((size_t)(b * 2 + 0) * IMG_H + h) * IMG_W + w];
    float fy = flow[((size_t)(b * 2 + 1) * IMG_H + h) * IMG_W + w];
    def[(size_t)idx * 2 + 0] = gx + fx * t;
    def[(size_t)idx * 2 + 1] = gy + fy * t;
}

// ---------------------------------------------------------------------------
// Patch extraction (grid_sample bilinear, zeros padding)
// ---------------------------------------------------------------------------
__global__ void patches_kernel(const float* __restrict__ x,
                               const float* __restrict__ def,
                               float* __restrict__ out)
{
    int bn = blockIdx.x;
    int b = bn >> 8;
    int n = bn & 255;
    int hy = n >> 4;
    int wx = n & 15;
    const float* dptr = def + (((size_t)(b * IMG_H + hy * STRIDE_) * IMG_W) + wx * STRIDE_) * 2;
    float cx = dptr[0];
    float cy = dptr[1];

    for (int p = threadIdx.x; p < PATCH * PATCH; p += blockDim.x) {
        int i = p >> 6;
        int j = p & 63;
        float pxv = -1.0f + 2.0f * (float)j / (float)(PATCH - 1);
        float pyv = -1.0f + 2.0f * (float)i / (float)(PATCH - 1);
        float gx = cx + pxv * ((float)PATCH / (float)IMG_W);
        float gy = cy + pyv * ((float)PATCH / (float)IMG_H);
        float ix = ((gx + 1.0f) * (float)IMG_W - 1.0f) * 0.5f;
        float iy = ((gy + 1.0f) * (float)IMG_H - 1.0f) * 0.5f;
        float x0f = floorf(ix), y0f = floorf(iy);
        float wx1 = ix - x0f, wy1 = iy - y0f;
        int x0 = (int)x0f, y0 = (int)y0f;
        int x1 = x0 + 1, y1 = y0 + 1;
        bool vx0 = (x0 >= 0) & (x0 <= IMG_W - 1);
        bool vx1 = (x1 >= 0) & (x1 <= IMG_W - 1);
        bool vy0 = (y0 >= 0) & (y0 <= IMG_H - 1);
        bool vy1 = (y1 >= 0) & (y1 <= IMG_H - 1);
        int x0c = min(max(x0, 0), IMG_W - 1);
        int x1c = min(max(x1, 0), IMG_W - 1);
        int y0c = min(max(y0, 0), IMG_H - 1);
        int y1c = min(max(y1, 0), IMG_H - 1);
        float w00 = (1.f - wx1) * (1.f - wy1) * (float)(vx0 && vy0);
        float w10 = wx1 * (1.f - wy1) * (float)(vx1 && vy0);
        float w01 = (1.f - wx1) * wy1 * (float)(vx0 && vy1);
        float w11 = wx1 * wy1 * (float)(vx1 && vy1);

#pragma unroll
        for (int c = 0; c < 3; c++) {
            const float* img = x + (size_t)(b * 3 + c) * IMG_H * IMG_W;
            float v = img[y0c * IMG_W + x0c] * w00
                    + img[y0c * IMG_W + x1c] * w10
                    + img[y1c * IMG_W + x0c] * w01
                    + img[y1c * IMG_W + x1c] * w11;
            out[((size_t)(bn)*3 + c) * (PATCH * PATCH) + p] = v;
        }
    }
}

// ---------------------------------------------------------------------------
// Launch
// ---------------------------------------------------------------------------
#define SMEM_C2_8 ((10 * 68 * 32 + 9 * 2 * 512) * 2 + 16)   // +mbar
#define SMEM_C4_4 ((10 * 36 * 32 + 9 * 4 * 512) * 2 + 16)
#define SMEM_C1_8 ((10 * 68 * 32 + 9 * 1 * 512) * 2 + 16)

extern "C" void kernel_launch(void* const* d_in, const int* in_sizes, int n_in,
                              void* d_out, int out_size)
{
    const float* x  = (const float*)d_in[0];
    const float* w0 = (const float*)d_in[1];  const float* b0 = (const float*)d_in[2];
    const float* w1 = (const float*)d_in[3];  const float* b1 = (const float*)d_in[4];
    const float* w2 = (const float*)d_in[5];  const float* b2 = (const float*)d_in[6];
    const float* w3 = (const float*)d_in[7];  const float* b3 = (const float*)d_in[8];
    const float* w4 = (const float*)d_in[9];  const float* b4 = (const float*)d_in[10];
    const float* w5 = (const float*)d_in[11]; const float* b5 = (const float*)d_in[12];
    const float* w6 = (const float*)d_in[13]; const float* b6 = (const float*)d_in[14];
    const float* w7 = (const float*)d_in[15]; const float* b7 = (const float*)d_in[16];
    const float* temp = (const float*)d_in[17];

    float* out     = (float*)d_out;
    float* patches = out;
    float* flow    = out + PATCHES_ELEMS;
    float* def     = out + PATCHES_ELEMS + FLOW_ELEMS;

    float* A;  cudaGetSymbolAddress((void**)&A, g_bufA);
    float* Bb; cudaGetSymbolAddress((void**)&Bb, g_bufB);
    __nv_bfloat16* WP; cudaGetSymbolAddress((void**)&WP, g_wpk);

    __nv_bfloat16* Apk = (__nv_bfloat16*)A;
    __nv_bfloat16* Bpk = (__nv_bfloat16*)Bb;

    cudaFuncSetAttribute((const void*)conv_mma_kernel<2, 8, 0, 1>,
                         cudaFuncAttributeMaxDynamicSharedMemorySize, SMEM_C2_8);
    cudaFuncSetAttribute((const void*)conv_mma_kernel<2, 8, 0, 0>,
                         cudaFuncAttributeMaxDynamicSharedMemorySize, SMEM_C2_8);
    cudaFuncSetAttribute((const void*)conv_mma_kernel<2, 8, 2, 0>,
                         cudaFuncAttributeMaxDynamicSharedMemorySize, SMEM_C2_8);
    cudaFuncSetAttribute((const void*)conv_mma_kernel<4, 4, 0, 0>,
                         cudaFuncAttributeMaxDynamicSharedMemorySize, SMEM_C4_4);
    cudaFuncSetAttribute((const void*)conv_mma_kernel<4, 4, 2, 0>,
                         cudaFuncAttributeMaxDynamicSharedMemorySize, SMEM_C4_4);
    cudaFuncSetAttribute((const void*)conv_mma_kernel<1, 8, 1, 0>,
                         cudaFuncAttributeMaxDynamicSharedMemorySize, SMEM_C1_8);

    // ---- preconvert ALL weights in one launch ----
    wconv_all<<<(WSCRATCH2 + 255) / 256, 256>>>(w0, w1, w2, w3, w4, w5, w6, w7, WP);

    // ---- flow net ----
    // conv0: 3->32 @512 relu, staged directly from fp32 x   (x -> A)
    conv_mma_kernel<2, 8, 0, 1><<<dim3(8, 64, 4), 256, SMEM_C2_8>>>(
        nullptr, x, WP + 0, b0, Apk, nullptr, 512, 512, 1, 32);
    // conv1+pool: 32->32 @512 relu -> 256²  (A -> B)
    conv_mma_kernel<2, 8, 2, 0><<<dim3(8, 64, 4), 256, SMEM_C2_8>>>(
        Apk, nullptr, WP + 9216, b1, Bpk, nullptr, 512, 512, 2, 32);
    // conv2: 32->64 @256 relu         (B -> A)
    conv_mma_kernel<4, 4, 0, 0><<<dim3(8, 32, 4), 256, SMEM_C4_4>>>(
        Bpk, nullptr, WP + 27648, b2, Apk, nullptr, 256, 256, 2, 64);
    // conv3+pool: 64->64 @256 relu -> 128²  (A -> B)
    conv_mma_kernel<4, 4, 2, 0><<<dim3(8, 32, 4), 256, SMEM_C4_4>>>(
        Apk, nullptr, WP + 64512, b3, Bpk, nullptr, 256, 256, 4, 64);
    // up: 128->256                    (B -> A)
    {
        int total = BATCH * 4 * 256 * 256 * 16;
        up_bf16<<<(total + 255) / 256, 256>>>(Bpk, Apk, total, 128, 128);
    }
    // conv4: 64->64 @256 relu         (A -> B)
    conv_mma_kernel<4, 4, 0, 0><<<dim3(8, 32, 4), 256, SMEM_C4_4>>>(
        Apk, nullptr, WP + 138240, b4, Bpk, nullptr, 256, 256, 4, 64);
    // conv5: 64->32 @256 relu         (B -> A)
    conv_mma_kernel<2, 8, 0, 0><<<dim3(4, 32, 4), 256, SMEM_C2_8>>>(
        Bpk, nullptr, WP + 211968, b5, Apk, nullptr, 256, 256, 4, 32);
    // up: 256->512                    (A -> B)
    {
        int total = BATCH * 2 * 512 * 512 * 16;
        up_bf16<<<(total + 255) / 256, 256>>>(Apk, Bpk, total, 256, 256);
    }
    // conv6: 32->32 @512 relu         (B -> A)
    conv_mma_kernel<2, 8, 0, 0><<<dim3(8, 64, 4), 256, SMEM_C2_8>>>(
        Bpk, nullptr, WP + 248832, b6, Apk, nullptr, 512, 512, 2, 32);
    // conv7: 32->2 @512 tanh          (A -> flow, fp32)
    conv_mma_kernel<1, 8, 1, 0><<<dim3(8, 64, 4), 256, SMEM_C1_8>>>(
        Apk, nullptr, WP + 267264, b7, nullptr, flow, 512, 512, 2, 2);

    // deformed grid
    {
        int total = BATCH * IMG_H * IMG_W;
        deform_kernel<<<(total + 255) / 256, 256>>>(flow, temp, def);
    }
    // patches
    patches_kernel<<<dim3(BATCH * NPATCH), 256>>>(x, def, patches);
}

// round 14
// speedup vs baseline: 1.6301x; 1.2120x over previous
#include <cuda_runtime.h>
#include <cuda_bf16.h>
#include <math.h>

// ---------------------------------------------------------------------------
// Problem constants
// ---------------------------------------------------------------------------
#define BATCH 4
#define IMG_H 512
#define IMG_W 512
#define PATCH 64
#define STRIDE_ 32
#define NPATCH 256
#define PATCHES_ELEMS (BATCH * NPATCH * 3 * PATCH * PATCH)   // 12,582,912
#define FLOW_ELEMS    (BATCH * 2 * IMG_H * IMG_W)            //  2,097,152

// Scratch (device globals). Activation = interleaved hi/lo, 32 bf16 per pixel.
__device__ __align__(256) float g_bufA[33554432];
__device__ __align__(256) float g_bufB[33554432];

// Packed weights: per (layer, cb, tap, ct): [32 lanes x 16B hi][32 lanes x 16B lo]
#define WSCRATCH2 276480
__device__ __align__(256) __nv_bfloat16 g_wpk[WSCRATCH2];

// ---------------------------------------------------------------------------
// helpers
// ---------------------------------------------------------------------------
__device__ __forceinline__ unsigned su32(const void* p) {
    return (unsigned)__cvta_generic_to_shared(p);
}
__device__ __forceinline__ void cp_async16(void* smem_dst, const void* gptr) {
    asm volatile("cp.async.cg.shared.global [%0], [%1], 16;"
                 :: "r"(su32(smem_dst)), "l"(gptr));
}
__device__ __forceinline__ void cp_commit() { asm volatile("cp.async.commit_group;"); }
__device__ __forceinline__ void cp_wait0()  { asm volatile("cp.async.wait_group 0;"); }

__device__ __forceinline__ void cp_bulk(unsigned sdst, const void* g, unsigned bytes,
                                        unsigned mbar) {
    asm volatile(
        "cp.async.bulk.shared::cta.global.mbarrier::complete_tx::bytes [%0], [%1], %2, [%3];"
        :: "r"(sdst), "l"(g), "r"(bytes), "r"(mbar) : "memory");
}
__device__ __forceinline__ void mbar_init(unsigned addr, unsigned cnt) {
    asm volatile("mbarrier.init.shared.b64 [%0], %1;" :: "r"(addr), "r"(cnt) : "memory");
}
__device__ __forceinline__ void mbar_expect_tx(unsigned addr, unsigned bytes) {
    asm volatile("mbarrier.arrive.expect_tx.shared.b64 _, [%0], %1;"
                 :: "r"(addr), "r"(bytes) : "memory");
}
__device__ __forceinline__ void mbar_wait(unsigned addr, unsigned parity) {
    asm volatile(
        "{\n\t.reg .pred P;\n\t"
        "W_%=:\n\t"
        "mbarrier.try_wait.parity.acquire.cta.shared::cta.b64 P, [%0], %1, 0x989680;\n\t"
        "@P bra.uni D_%=;\n\t"
        "bra.uni W_%=;\n\t"
        "D_%=:\n\t}"
        :: "r"(addr), "r"(parity) : "memory");
}

__device__ __forceinline__ void mma16816(float* c, const unsigned* a, unsigned b0, unsigned b1) {
    asm volatile(
        "mma.sync.aligned.m16n8k16.row.col.f32.bf16.bf16.f32 "
        "{%0,%1,%2,%3}, {%4,%5,%6,%7}, {%8,%9}, {%0,%1,%2,%3};"
        : "+f"(c[0]), "+f"(c[1]), "+f"(c[2]), "+f"(c[3])
        : "r"(a[0]), "r"(a[1]), "r"(a[2]), "r"(a[3]), "r"(b0), "r"(b1));
}

// slot permutation within 16 channels
__device__ __forceinline__ int pos16(int ci) {
    return (((ci >> 1) & 3) << 2) + (((ci >> 3) & 1) << 1) + (ci & 1);
}
// interleaved layout: hi offset = 8*(s>>2)+(s&3), lo = +4
__device__ __forceinline__ int hoff16(int s) { return 8 * (s >> 2) + (s & 3); }

__device__ __forceinline__ void bf16split(float v, __nv_bfloat16& h, __nv_bfloat16& l) {
    h = __float2bfloat16(v);
    l = __float2bfloat16(v - __bfloat162float(h));
}

// ---------------------------------------------------------------------------
// Fused weight preconversion: fp32 -> packed per-lane mma A-fragments.
// ---------------------------------------------------------------------------
__constant__ int c_woffs2[9] = {0, 9216, 27648, 64512, 138240, 211968, 248832, 267264, 276480};
__constant__ int c_wCOUT[8]  = {32, 32, 64, 64, 64, 32, 32, 2};
__constant__ int c_wCIN[8]   = {3, 32, 32, 64, 64, 64, 32, 32};
__constant__ int c_wNCT[8]   = {2, 2, 4, 4, 4, 2, 2, 1};

__global__ void wconv_all(const float* __restrict__ w0, const float* __restrict__ w1,
                          const float* __restrict__ w2, const float* __restrict__ w3,
                          const float* __restrict__ w4, const float* __restrict__ w5,
                          const float* __restrict__ w6, const float* __restrict__ w7,
                          __nv_bfloat16* __restrict__ dst)
{
    int idx = blockIdx.x * blockDim.x + threadIdx.x;
    if (idx >= WSCRATCH2) return;
    int l = 0;
    while (idx >= c_woffs2[l + 1]) l++;
    int rel = idx - c_woffs2[l];
    int COUT = c_wCOUT[l], CIN = c_wCIN[l], NCT = c_wNCT[l];
    int e    = rel & 255;
    int plane = (rel >> 8) & 1;
    int unit = rel >> 9;
    int ct  = unit % NCT;  unit /= NCT;
    int tap = unit % 9;
    int cb  = unit / 9;
    int lane = e >> 3;
    int e8 = e & 7;
    int j = e8 >> 1, kk = e8 & 1;
    int gid = lane >> 2, q = lane & 3;
    int co = ct * 16 + gid + (j & 1) * 8;
    int k  = 2 * q + kk + ((j & 2) ? 8 : 0);
    int ci_g = cb * 16 + k;
    const float* w;
    switch (l) {
        case 0: w = w0; break; case 1: w = w1; break;
        case 2: w = w2; break; case 3: w = w3; break;
        case 4: w = w4; break; case 5: w = w5; break;
        case 6: w = w6; break; default: w = w7; break;
    }
    float v = 0.f;
    if (co < COUT && ci_g < CIN)
        v = w[((size_t)co * CIN + ci_g) * 9 + tap];
    __nv_bfloat16 h = __float2bfloat16(v);
    dst[idx] = plane ? __float2bfloat16(v - __bfloat162float(h)) : h;
}

// ---------------------------------------------------------------------------
// Implicit-GEMM 3x3 conv via mma.sync bf16 (3-term hi/lo split), layout v2.
// Tile: (NT*8) wide x 8 tall x (NCT*16) couts. 256 threads (8 warps).
// Double-buffered input staging via cp.async.bulk + 3 mbarriers (INX=0);
// direct fp32->bf16 conversion from x (INX=1, conv0 only).
// OUTMODE: 0 = act layout (+relu); 1 = fp32 NCHW (+tanh);
//          2 = act layout, fused bias+relu+MaxPool2x2
// ---------------------------------------------------------------------------
template <int NCT, int NT, int OUTMODE, int INX>
__global__ void __launch_bounds__(256, 2)
conv_mma_kernel(const __nv_bfloat16* __restrict__ gact,
                const float* __restrict__ xin,
                const __nv_bfloat16* __restrict__ gw,
                const float* __restrict__ bias,
                __nv_bfloat16* __restrict__ oact,
                float* __restrict__ of32,
                int H, int W, int CBIN, int COUT)
{
    constexpr int COUTP = NCT * 16;
    constexpr int TILEW = NT * 8;
    constexpr int PITCH = TILEW + 4;
    constexpr int INP = 10 * PITCH * 32;      // bf16 per input buffer
    constexpr int WPL = 9 * NCT * 512;        // bf16 per weight chunk
    extern __shared__ char smraw[];
    __nv_bfloat16* s_in0 = (__nv_bfloat16*)smraw;
    __nv_bfloat16* s_in1 = s_in0 + INP;
    __nv_bfloat16* s_w   = s_in0 + 2 * INP;
    const unsigned mb_base = su32(smraw) + (2 * INP + WPL) * 2;
    const unsigned mb_in0 = mb_base, mb_in1 = mb_base + 8, mb_w = mb_base + 16;

    const int bx = blockIdx.x * TILEW;
    const int by = blockIdx.y * 8;
    const int b  = blockIdx.z;

    const int tid  = threadIdx.x;
    const int warp = tid >> 5;
    const int lane = tid & 31;
    const int gid  = lane >> 2;
    const int qid  = lane & 3;

    float acc[NCT][NT][4];
#pragma unroll
    for (int ct = 0; ct < NCT; ct++)
#pragma unroll
        for (int nt = 0; nt < NT; nt++) {
            acc[ct][nt][0] = 0.f; acc[ct][nt][1] = 0.f;
            acc[ct][nt][2] = 0.f; acc[ct][nt][3] = 0.f;
        }

    // halo geometry (static per CTA)
    const int r0 = (by == 0) ? 1 : 0;
    const int r1 = (by + 8 >= H) ? 9 : 10;
    const int c0 = (bx == 0) ? 1 : 0;
    const int c1 = (bx + TILEW >= W) ? (TILEW + 1) : (TILEW + 2);
    const unsigned rowBytes = (unsigned)(c1 - c0) * 64u;
    const unsigned inBytes  = (unsigned)(r1 - r0) * rowBytes;

    if (!INX) {
        if (tid == 0) {
            mbar_init(mb_in0, 1);
            mbar_init(mb_in1, 1);
            mbar_init(mb_w, 1);
        }
        // zero-fill OOB halo ONCE in BOTH buffers
        for (int p = tid; p < 10 * (TILEW + 2); p += 256) {
            int row = p / (TILEW + 2);
            int col = p - row * (TILEW + 2);
            if (row < r0 || row >= r1 || col < c0 || col >= c1) {
                uint4 z = make_uint4(0u, 0u, 0u, 0u);
                uint4* d0 = (uint4*)(s_in0 + (row * PITCH + col) * 32);
                uint4* d1 = (uint4*)(s_in1 + (row * PITCH + col) * 32);
                d0[0] = z; d0[1] = z; d0[2] = z; d0[3] = z;
                d1[0] = z; d1[1] = z; d1[2] = z; d1[3] = z;
            }
        }
        __syncthreads();   // init + zero-fill visible before staging/waits
        if (tid == 0) {
            // prologue: input chunk 0 + weights chunk 0
            mbar_expect_tx(mb_in0, inBytes);
            for (int r = r0; r < r1; r++) {
                int gy = by + r - 1;
                const __nv_bfloat16* src = gact +
                    ((((size_t)b * CBIN + 0) * H + gy) * W + (bx + c0 - 1)) * 32;
                cp_bulk(su32(s_in0 + (r * PITCH + c0) * 32), src, rowBytes, mb_in0);
            }
            mbar_expect_tx(mb_w, (unsigned)WPL * 2u);
            cp_bulk(su32(s_w), gw, (unsigned)WPL * 2u, mb_w);
        }
    }

    int ph_in0 = 0, ph_in1 = 0, ph_w = 0;

    for (int cb = 0; cb < CBIN; cb++) {
        const int buf = cb & 1;
        if (INX) {
            __syncthreads();
            for (int idx = tid * 8; idx < WPL; idx += 2048)
                cp_async16(s_w + idx, gw + idx);
            for (int p = tid; p < 10 * (TILEW + 2); p += 256) {
                int row = p / (TILEW + 2);
                int col = p - row * (TILEW + 2);
                int gy = by + row - 1;
                int gx = bx + col - 1;
                __nv_bfloat16 arr[32];
#pragma unroll
                for (int i = 0; i < 32; i++) arr[i] = __float2bfloat16(0.f);
                if (gy >= 0 && gy < H && gx >= 0 && gx < W) {
#pragma unroll
                    for (int ci = 0; ci < 3; ci++) {
                        float v = xin[((size_t)(b * 3 + ci) * H + gy) * W + gx];
                        __nv_bfloat16 h, l;
                        bf16split(v, h, l);
                        int hf = hoff16(pos16(ci));
                        arr[hf] = h;
                        arr[hf + 4] = l;
                    }
                }
                uint4* src = (uint4*)arr;
                uint4* dst = (uint4*)(s_in0 + (row * PITCH + col) * 32);
                dst[0] = src[0]; dst[1] = src[1]; dst[2] = src[2]; dst[3] = src[3];
            }
            cp_commit();
            cp_wait0();
            __syncthreads();
        } else {
            // issue input prefetch for chunk cb+1 into the other buffer
            if (tid == 0 && cb + 1 < CBIN) {
                unsigned mb_n = buf ? mb_in0 : mb_in1;
                __nv_bfloat16* s_n = buf ? s_in0 : s_in1;
                mbar_expect_tx(mb_n, inBytes);
                for (int r = r0; r < r1; r++) {
                    int gy = by + r - 1;
                    const __nv_bfloat16* src = gact +
                        ((((size_t)b * CBIN + (cb + 1)) * H + gy) * W + (bx + c0 - 1)) * 32;
                    cp_bulk(su32(s_n + (r * PITCH + c0) * 32), src, rowBytes, mb_n);
                }
            }
            // wait current input + weights
            if (buf == 0) { mbar_wait(mb_in0, (unsigned)ph_in0); ph_in0 ^= 1; }
            else          { mbar_wait(mb_in1, (unsigned)ph_in1); ph_in1 ^= 1; }
            mbar_wait(mb_w, (unsigned)ph_w); ph_w ^= 1;
        }

        const __nv_bfloat16* s_act = buf ? s_in1 : s_in0;

        // ---- compute: 9 taps ----
        int ky = 0, kx = 0;
#pragma unroll 1
        for (int tap = 0; tap < 9; tap++) {
            unsigned ah[NCT][4], al[NCT][4];
            const int wb = tap * NCT * 512 + lane * 8;
#pragma unroll
            for (int ct = 0; ct < NCT; ct++) {
                uint4 hv = *(const uint4*)(s_w + wb + ct * 512);
                uint4 lv = *(const uint4*)(s_w + wb + ct * 512 + 256);
                ah[ct][0] = hv.x; ah[ct][1] = hv.y; ah[ct][2] = hv.z; ah[ct][3] = hv.w;
                al[ct][0] = lv.x; al[ct][1] = lv.y; al[ct][2] = lv.z; al[ct][3] = lv.w;
            }
            const int rowb = warp + ky;
#pragma unroll
            for (int nt = 0; nt < NT; nt++) {
                int colb = nt * 8 + gid + kx;
                uint4 bv = *(const uint4*)(s_act + (rowb * PITCH + colb) * 32 + 8 * qid);
#pragma unroll
                for (int ct = 0; ct < NCT; ct++) {
                    mma16816(acc[ct][nt], ah[ct], bv.x, bv.y);
                    mma16816(acc[ct][nt], ah[ct], bv.z, bv.w);
                    mma16816(acc[ct][nt], al[ct], bv.x, bv.y);
                }
            }
            if (++kx == 3) { kx = 0; ++ky; }
        }

        if (!INX && cb + 1 < CBIN) {
            __syncthreads();   // all warps done with s_w before overwrite
            if (tid == 0) {
                mbar_expect_tx(mb_w, (unsigned)WPL * 2u);
                cp_bulk(su32(s_w), gw + (size_t)(cb + 1) * WPL, (unsigned)WPL * 2u, mb_w);
            }
        }
    }

    // ---- epilogue ----
    const int gy = by + warp;
    if (OUTMODE == 1) {
#pragma unroll
        for (int ct = 0; ct < NCT; ct++) {
            int co0r = ct * 16 + gid;
            int co1r = co0r + 8;
            bool ok0 = co0r < COUT;
            bool ok1 = co1r < COUT;
            float bv0 = ok0 ? bias[co0r] : 0.f;
            float bv1 = ok1 ? bias[co1r] : 0.f;
#pragma unroll
            for (int nt = 0; nt < NT; nt++) {
                int gxv = bx + nt * 8 + 2 * qid;
                if (ok0) {
                    float v0 = tanhf(acc[ct][nt][0] + bv0);
                    float v1 = tanhf(acc[ct][nt][1] + bv0);
                    *(float2*)&of32[((size_t)(b * COUT + co0r) * H + gy) * W + gxv]
                        = make_float2(v0, v1);
                }
                if (ok1) {
                    float v0 = tanhf(acc[ct][nt][2] + bv1);
                    float v1 = tanhf(acc[ct][nt][3] + bv1);
                    *(float2*)&of32[((size_t)(b * COUT + co1r) * H + gy) * W + gxv]
                        = make_float2(v0, v1);
                }
            }
        }
    } else if (OUTMODE == 0) {
        const int nCBo = COUT >> 4;
        const int s0 = 4 * (gid >> 1) + (gid & 1);
        const int hf0 = hoff16(s0);
        const int hf1 = hf0 + 2;
#pragma unroll
        for (int ct = 0; ct < NCT; ct++) {
            int co_g = ct * 16 + gid;
            int cbo = co_g >> 4;
            float bv0 = bias[co_g];
            float bv1 = bias[co_g + 8];
#pragma unroll
            for (int nt = 0; nt < NT; nt++) {
                int gxv = bx + nt * 8 + 2 * qid;
                size_t g = ((((size_t)b * nCBo + cbo) * H + gy) * W + gxv) * 32;
                float v0 = fmaxf(acc[ct][nt][0] + bv0, 0.f);
                float v1 = fmaxf(acc[ct][nt][1] + bv0, 0.f);
                float v2 = fmaxf(acc[ct][nt][2] + bv1, 0.f);
                float v3 = fmaxf(acc[ct][nt][3] + bv1, 0.f);
                __nv_bfloat16 h, l;
                bf16split(v0, h, l); oact[g + hf0]          = h; oact[g + hf0 + 4]      = l;
                bf16split(v1, h, l); oact[g + 32 + hf0]     = h; oact[g + 32 + hf0 + 4] = l;
                bf16split(v2, h, l); oact[g + hf1]          = h; oact[g + hf1 + 4]      = l;
                bf16split(v3, h, l); oact[g + 32 + hf1]     = h; oact[g + 32 + hf1 + 4] = l;
            }
        }
    } else {
        // OUTMODE 2: fused bias + relu + MaxPool 2x2
        constexpr int PW = NT * 4;
        constexpr int PC = COUTP + 1;
        float* s_pool = (float*)smraw;
        __syncthreads();
#pragma unroll
        for (int ct = 0; ct < NCT; ct++) {
            float bv0 = bias[ct * 16 + gid];
            float bv1 = bias[ct * 16 + 8 + gid];
#pragma unroll
            for (int nt = 0; nt < NT; nt++) {
                float v0 = fmaxf(acc[ct][nt][0] + bv0, 0.f);
                float v1 = fmaxf(acc[ct][nt][1] + bv0, 0.f);
                float v2 = fmaxf(acc[ct][nt][2] + bv1, 0.f);
                float v3 = fmaxf(acc[ct][nt][3] + bv1, 0.f);
                int px = nt * 4 + qid;
                s_pool[(warp * PW + px) * PC + ct * 16 + gid]     = fmaxf(v0, v1);
                s_pool[(warp * PW + px) * PC + ct * 16 + 8 + gid] = fmaxf(v2, v3);
            }
        }
        __syncthreads();
        const int H2 = H >> 1, W2 = W >> 1;
        const int nCBo = COUT >> 4;
        constexpr int TOTP = 4 * PW * COUTP;
        for (int v = tid; v < TOTP; v += 256) {
            int co = v & (COUTP - 1);
            int rest = v >> (NCT == 4 ? 6 : 5);
            int px = rest & (PW - 1);
            int prow = rest / PW;
            float a = s_pool[((2 * prow) * PW + px) * PC + co];
            float bq = s_pool[((2 * prow + 1) * PW + px) * PC + co];
            float m = fmaxf(a, bq);
            int gy2 = (by >> 1) + prow;
            int gx2 = (bx >> 1) + px;
            int cbo = co >> 4;
            int hf = hoff16(pos16(co & 15));
            size_t g = ((((size_t)b * nCBo + cbo) * H2 + gy2) * W2 + gx2) * 32;
            __nv_bfloat16 h, l;
            bf16split(m, h, l);
            oact[g + hf] = h;
            oact[g + hf + 4] = l;
        }
    }
}

// ---------------------------------------------------------------------------
// Bilinear upsample x2, vectorized: 1 thread per output pixel (32 bf16).
// ---------------------------------------------------------------------------
__global__ void up_bf16_v2(const __nv_bfloat16* __restrict__ iact,
                           __nv_bfloat16* __restrict__ oact,
                           int total, int Hin, int Win)
{
    int p = blockIdx.x * blockDim.x + threadIdx.x;
    if (p >= total) return;
    int Hout = 2 * Hin, Wout = 2 * Win;
    int ox = p % Wout;
    int t = p / Wout;
    int oy = t % Hout;
    int c = t / Hout;

    float fy = (oy + 0.5f) * 0.5f - 0.5f;
    float fx = (ox + 0.5f) * 0.5f - 0.5f;
    int y0 = (int)floorf(fy);
    int x0 = (int)floorf(fx);
    float wy = fy - (float)y0;
    float wx = fx - (float)x0;
    int y0c = max(y0, 0), y1c = min(y0 + 1, Hin - 1);
    int x0c = max(x0, 0), x1c = min(x0 + 1, Win - 1);
    float w00 = (1.f - wy) * (1.f - wx), w01 = (1.f - wy) * wx;
    float w10 = wy * (1.f - wx),         w11 = wy * wx;

    size_t cb = (size_t)c * Hin;
    const uint4* p00 = (const uint4*)(iact + ((cb + y0c) * Win + x0c) * 32);
    const uint4* p01 = (const uint4*)(iact + ((cb + y0c) * Win + x1c) * 32);
    const uint4* p10 = (const uint4*)(iact + ((cb + y1c) * Win + x0c) * 32);
    const uint4* p11 = (const uint4*)(iact + ((cb + y1c) * Win + x1c) * 32);

    __nv_bfloat16 a00[32], a01[32], a10[32], a11[32], o[32];
#pragma unroll
    for (int i = 0; i < 4; i++) {
        ((uint4*)a00)[i] = p00[i];
        ((uint4*)a01)[i] = p01[i];
        ((uint4*)a10)[i] = p10[i];
        ((uint4*)a11)[i] = p11[i];
    }
#pragma unroll
    for (int g = 0; g < 4; g++) {
#pragma unroll
        for (int k = 0; k < 4; k++) {
            int hi = 8 * g + k, lo = hi + 4;
            float v00 = __bfloat162float(a00[hi]) + __bfloat162float(a00[lo]);
            float v01 = __bfloat162float(a01[hi]) + __bfloat162float(a01[lo]);
            float v10 = __bfloat162float(a10[hi]) + __bfloat162float(a10[lo]);
            float v11 = __bfloat162float(a11[hi]) + __bfloat162float(a11[lo]);
            float v = w00 * v00 + w01 * v01 + w10 * v10 + w11 * v11;
            __nv_bfloat16 h, l;
            bf16split(v, h, l);
            o[hi] = h;
            o[lo] = l;
        }
    }
    uint4* dst = (uint4*)(oact + (size_t)p * 32);
#pragma unroll
    for (int i = 0; i < 4; i++) dst[i] = ((uint4*)o)[i];
}

// ---------------------------------------------------------------------------
// deformed = base_grid + flow^T * temp
// ---------------------------------------------------------------------------
__global__ void deform_kernel(const float* __restrict__ flow,
                              const float* __restrict__ temp,
                              float* __restrict__ def)
{
    int idx = blockIdx.x * blockDim.x + threadIdx.x;
    int total = BATCH * IMG_H * IMG_W;
    if (idx >= total) return;
    int w = idx % IMG_W;
    int h = (idx / IMG_W) % IMG_H;
    int b = idx / (IMG_W * IMG_H);
    float gx = -1.0f + 2.0f * (float)w / (float)(IMG_W - 1);
    float gy = -1.0f + 2.0f * (float)h / (float)(IMG_H - 1);
    float t = temp[0];
    float fx = flow[((size_t)(b * 2 + 0) * IMG_H + h) * IMG_W + w];
    float fy = flow[((size_t)(b * 2 + 1) * IMG_H + h) * IMG_W + w];
    def[(size_t)idx * 2 + 0] = gx + fx * t;
    def[(size_t)idx * 2 + 1] = gy + fy * t;
}

// ---------------------------------------------------------------------------
// Patch extraction (grid_sample bilinear, zeros padding)
// ---------------------------------------------------------------------------
__global__ void patches_kernel(const float* __restrict__ x,
                               const float* __restrict__ def,
                               float* __restrict__ out)
{
    int bn = blockIdx.x;
    int b = bn >> 8;
    int n = bn & 255;
    int hy = n >> 4;
    int wx = n & 15;
    const float* dptr = def + (((size_t)(b * IMG_H + hy * STRIDE_) * IMG_W) + wx * STRIDE_) * 2;
    float cx = dptr[0];
    float cy = dptr[1];

    for (int p = threadIdx.x; p < PATCH * PATCH; p += blockDim.x) {
        int i = p >> 6;
        int j = p & 63;
        float pxv = -1.0f + 2.0f * (float)j / (float)(PATCH - 1);
        float pyv = -1.0f + 2.0f * (float)i / (float)(PATCH - 1);
        float gx = cx + pxv * ((float)PATCH / (float)IMG_W);
        float gy = cy + pyv * ((float)PATCH / (float)IMG_H);
        float ix = ((gx + 1.0f) * (float)IMG_W - 1.0f) * 0.5f;
        float iy = ((gy + 1.0f) * (float)IMG_H - 1.0f) * 0.5f;
        float x0f = floorf(ix), y0f = floorf(iy);
        float wx1 = ix - x0f, wy1 = iy - y0f;
        int x0 = (int)x0f, y0 = (int)y0f;
        int x1 = x0 + 1, y1 = y0 + 1;
        bool vx0 = (x0 >= 0) & (x0 <= IMG_W - 1);
        bool vx1 = (x1 >= 0) & (x1 <= IMG_W - 1);
        bool vy0 = (y0 >= 0) & (y0 <= IMG_H - 1);
        bool vy1 = (y1 >= 0) & (y1 <= IMG_H - 1);
        int x0c = min(max(x0, 0), IMG_W - 1);
        int x1c = min(max(x1, 0), IMG_W - 1);
        int y0c = min(max(y0, 0), IMG_H - 1);
        int y1c = min(max(y1, 0), IMG_H - 1);
        float w00 = (1.f - wx1) * (1.f - wy1) * (float)(vx0 && vy0);
        float w10 = wx1 * (1.f - wy1) * (float)(vx1 && vy0);
        float w01 = (1.f - wx1) * wy1 * (float)(vx0 && vy1);
        float w11 = wx1 * wy1 * (float)(vx1 && vy1);

#pragma unroll
        for (int c = 0; c < 3; c++) {
            const float* img = x + (size_t)(b * 3 + c) * IMG_H * IMG_W;
            float v = img[y0c * IMG_W + x0c] * w00
                    + img[y0c * IMG_W + x1c] * w10
                    + img[y1c * IMG_W + x0c] * w01
                    + img[y1c * IMG_W + x1c] * w11;
            out[((size_t)(bn)*3 + c) * (PATCH * PATCH) + p] = v;
        }
    }
}

// ---------------------------------------------------------------------------
// Launch
// ---------------------------------------------------------------------------
#define SMEM_C2_8 ((2 * 10 * 68 * 32 + 9 * 2 * 512) * 2 + 32)   // 105,504 B
#define SMEM_C4_4 ((2 * 10 * 36 * 32 + 9 * 4 * 512) * 2 + 32)   //  82,976 B
#define SMEM_C1_8 ((2 * 10 * 68 * 32 + 9 * 1 * 512) * 2 + 32)   //  96,288 B

extern "C" void kernel_launch(void* const* d_in, const int* in_sizes, int n_in,
                              void* d_out, int out_size)
{
    const float* x  = (const float*)d_in[0];
    const float* w0 = (const float*)d_in[1];  const float* b0 = (const float*)d_in[2];
    const float* w1 = (const float*)d_in[3];  const float* b1 = (const float*)d_in[4];
    const float* w2 = (const float*)d_in[5];  const float* b2 = (const float*)d_in[6];
    const float* w3 = (const float*)d_in[7];  const float* b3 = (const float*)d_in[8];
    const float* w4 = (const float*)d_in[9];  const float* b4 = (const float*)d_in[10];
    const float* w5 = (const float*)d_in[11]; const float* b5 = (const float*)d_in[12];
    const float* w6 = (const float*)d_in[13]; const float* b6 = (const float*)d_in[14];
    const float* w7 = (const float*)d_in[15]; const float* b7 = (const float*)d_in[16];
    const float* temp = (const float*)d_in[17];

    float* out     = (float*)d_out;
    float* patches = out;
    float* flow    = out + PATCHES_ELEMS;
    float* def     = out + PATCHES_ELEMS + FLOW_ELEMS;

    float* A;  cudaGetSymbolAddress((void**)&A, g_bufA);
    float* Bb; cudaGetSymbolAddress((void**)&Bb, g_bufB);
    __nv_bfloat16* WP; cudaGetSymbolAddress((void**)&WP, g_wpk);

    __nv_bfloat16* Apk = (__nv_bfloat16*)A;
    __nv_bfloat16* Bpk = (__nv_bfloat16*)Bb;

    cudaFuncSetAttribute((const void*)conv_mma_kernel<2, 8, 0, 1>,
                         cudaFuncAttributeMaxDynamicSharedMemorySize, SMEM_C2_8);
    cudaFuncSetAttribute((const void*)conv_mma_kernel<2, 8, 0, 0>,
                         cudaFuncAttributeMaxDynamicSharedMemorySize, SMEM_C2_8);
    cudaFuncSetAttribute((const void*)conv_mma_kernel<2, 8, 2, 0>,
                         cudaFuncAttributeMaxDynamicSharedMemorySize, SMEM_C2_8);
    cudaFuncSetAttribute((const void*)conv_mma_kernel<4, 4, 0, 0>,
                         cudaFuncAttributeMaxDynamicSharedMemorySize, SMEM_C4_4);
    cudaFuncSetAttribute((const void*)conv_mma_kernel<4, 4, 2, 0>,
                         cudaFuncAttributeMaxDynamicSharedMemorySize, SMEM_C4_4);
    cudaFuncSetAttribute((const void*)conv_mma_kernel<1, 8, 1, 0>,
                         cudaFuncAttributeMaxDynamicSharedMemorySize, SMEM_C1_8);

    // ---- preconvert ALL weights in one launch ----
    wconv_all<<<(WSCRATCH2 + 255) / 256, 256>>>(w0, w1, w2, w3, w4, w5, w6, w7, WP);

    // ---- flow net ----
    // conv0: 3->32 @512 relu, staged directly from fp32 x   (x -> A)
    conv_mma_kernel<2, 8, 0, 1><<<dim3(8, 64, 4), 256, SMEM_C2_8>>>(
        nullptr, x, WP + 0, b0, Apk, nullptr, 512, 512, 1, 32);
    // conv1+pool: 32->32 @512 relu -> 256²  (A -> B)
    conv_mma_kernel<2, 8, 2, 0><<<dim3(8, 64, 4), 256, SMEM_C2_8>>>(
        Apk, nullptr, WP + 9216, b1, Bpk, nullptr, 512, 512, 2, 32);
    // conv2: 32->64 @256 relu         (B -> A)
    conv_mma_kernel<4, 4, 0, 0><<<dim3(8, 32, 4), 256, SMEM_C4_4>>>(
        Bpk, nullptr, WP + 27648, b2, Apk, nullptr, 256, 256, 2, 64);
    // conv3+pool: 64->64 @256 relu -> 128²  (A -> B)
    conv_mma_kernel<4, 4, 2, 0><<<dim3(8, 32, 4), 256, SMEM_C4_4>>>(
        Apk, nullptr, WP + 64512, b3, Bpk, nullptr, 256, 256, 4, 64);
    // up: 128->256                    (B -> A)
    {
        int total = BATCH * 4 * 256 * 256;
        up_bf16_v2<<<(total + 255) / 256, 256>>>(Bpk, Apk, total, 128, 128);
    }
    // conv4: 64->64 @256 relu         (A -> B)
    conv_mma_kernel<4, 4, 0, 0><<<dim3(8, 32, 4), 256, SMEM_C4_4>>>(
        Apk, nullptr, WP + 138240, b4, Bpk, nullptr, 256, 256, 4, 64);
    // conv5: 64->32 @256 relu         (B -> A)
    conv_mma_kernel<2, 8, 0, 0><<<dim3(4, 32, 4), 256, SMEM_C2_8>>>(
        Bpk, nullptr, WP + 211968, b5, Apk, nullptr, 256, 256, 4, 32);
    // up: 256->512                    (A -> B)
    {
        int total = BATCH * 2 * 512 * 512;
        up_bf16_v2<<<(total + 255) / 256, 256>>>(Apk, Bpk, total, 256, 256);
    }
    // conv6: 32->32 @512 relu         (B -> A)
    conv_mma_kernel<2, 8, 0, 0><<<dim3(8, 64, 4), 256, SMEM_C2_8>>>(
        Bpk, nullptr, WP + 248832, b6, Apk, nullptr, 512, 512, 2, 32);
    // conv7: 32->2 @512 tanh          (A -> flow, fp32)
    conv_mma_kernel<1, 8, 1, 0><<<dim3(8, 64, 4), 256, SMEM_C1_8>>>(
        Apk, nullptr, WP + 267264, b7, nullptr, flow, 512, 512, 2, 2);

    // deformed grid
    {
        int total = BATCH * IMG_H * IMG_W;
        deform_kernel<<<(total + 255) / 256, 256>>>(flow, temp, def);
    }
    // patches
    patches_kernel<<<dim3(BATCH * NPATCH), 256>>>(x, def, patches);
}